// round 1
// baseline (speedup 1.0000x reference)
#include <cuda_runtime.h>
#include <cuda_bf16.h>
#include <cstddef>

using ull = unsigned long long;

// ---------------- packed f32x2 helpers (Blackwell FFMA2 path) ----------------
__device__ __forceinline__ ull pack2(float x, float y) {
    ull r; asm("mov.b64 %0, {%1, %2};" : "=l"(r) : "f"(x), "f"(y)); return r;
}
__device__ __forceinline__ void unpack2(ull v, float& x, float& y) {
    asm("mov.b64 {%0, %1}, %2;" : "=f"(x), "=f"(y) : "l"(v));
}
__device__ __forceinline__ ull ffma2(ull a, ull b, ull c) {
    ull d; asm("fma.rn.f32x2 %0, %1, %2, %3;" : "=l"(d) : "l"(a), "l"(b), "l"(c)); return d;
}
__device__ __forceinline__ ull mul2(ull a, ull b) {
    ull d; asm("mul.rn.f32x2 %0, %1, %2;" : "=l"(d) : "l"(a), "l"(b)); return d;
}

// ---------------- problem constants ----------------
#define BATCH 2
#define SEQ   2048
#define DMODEL 1024
#define NH    16
#define NKV   4
#define HD    64
#define ROWS  (BATCH*SEQ)     // 4096

// scratch (device globals; no allocation allowed)
__device__ float g_Q[ROWS * DMODEL];   // Q after projection+rope: [4096,1024]
__device__ float g_AO[ROWS * DMODEL];  // attention output before Wo

// ---------------- SGEMM: C[M,N] = A[M,K] @ B[K,N], row-major, fp32 ----------------
// BM=128, BN=128, BK=8, 256 threads, 8x8 per thread, f32x2 accumulators.
// Requires M%128==0, N%128==0, K%8==0, 16B-aligned pointers.
#define LDA_S 132
__global__ __launch_bounds__(256) void sgemm_kernel(
    const float* __restrict__ A, const float* __restrict__ B, float* __restrict__ C,
    int M, int N, int K)
{
    __shared__ float As[8 * LDA_S];   // transposed A tile [k][row], padded
    __shared__ float Bs[8 * 128];     // B tile [k][col]

    const int tid  = threadIdx.x;
    const int brow = blockIdx.y * 128;
    const int bcol = blockIdx.x * 128;

    const int ty = tid >> 4;          // 0..15 -> row group
    const int tx = tid & 15;          // 0..15 -> col group

    const int arow = tid >> 1;        // 0..127
    const int acol = (tid & 1) * 4;   // 0 or 4
    const int brw  = tid >> 5;        // 0..7
    const int bcl  = (tid & 31) * 4;  // 0..124

    ull acc[8][4];
#pragma unroll
    for (int i = 0; i < 8; i++)
#pragma unroll
        for (int j = 0; j < 4; j++) acc[i][j] = 0ULL;

    for (int k0 = 0; k0 < K; k0 += 8) {
        float4 a = *(const float4*)(A + (size_t)(brow + arow) * K + k0 + acol);
        As[(acol + 0) * LDA_S + arow] = a.x;
        As[(acol + 1) * LDA_S + arow] = a.y;
        As[(acol + 2) * LDA_S + arow] = a.z;
        As[(acol + 3) * LDA_S + arow] = a.w;
        float4 b4 = *(const float4*)(B + (size_t)(k0 + brw) * N + bcol + bcl);
        *(float4*)&Bs[brw * 128 + bcl] = b4;
        __syncthreads();

#pragma unroll
        for (int kk = 0; kk < 8; kk++) {
            float4 a0 = *(const float4*)&As[kk * LDA_S + ty * 8];
            float4 a1 = *(const float4*)&As[kk * LDA_S + ty * 8 + 4];
            const ull* bp = (const ull*)&Bs[kk * 128 + tx * 8];
            ull b0 = bp[0], b1 = bp[1], b2 = bp[2], b3 = bp[3];
            float av[8] = {a0.x, a0.y, a0.z, a0.w, a1.x, a1.y, a1.z, a1.w};
#pragma unroll
            for (int i = 0; i < 8; i++) {
                ull aa = pack2(av[i], av[i]);
                acc[i][0] = ffma2(aa, b0, acc[i][0]);
                acc[i][1] = ffma2(aa, b1, acc[i][1]);
                acc[i][2] = ffma2(aa, b2, acc[i][2]);
                acc[i][3] = ffma2(aa, b3, acc[i][3]);
            }
        }
        __syncthreads();
    }

#pragma unroll
    for (int i = 0; i < 8; i++) {
        float* crow = C + (size_t)(brow + ty * 8 + i) * N + bcol + tx * 8;
#pragma unroll
        for (int j = 0; j < 4; j++) {
            *(ull*)&crow[2 * j] = acc[i][j];   // packed bits == {f.x, f.y}
        }
    }
}

// ---------------- RoPE (in place) ----------------
// X: [rows=4096][heads*64]. pairs (d, d+32) per head, d<32. s = row % SEQ.
__global__ void rope_kernel(float* __restrict__ X,
                            const float* __restrict__ cosT,
                            const float* __restrict__ sinT,
                            int heads, int total)
{
    int idx = blockIdx.x * blockDim.x + threadIdx.x;
    if (idx >= total) return;
    int d    = idx & 31;
    int rest = idx >> 5;
    int head = rest % heads;
    int row  = rest / heads;
    int s    = row & (SEQ - 1);
    float c  = cosT[s * 32 + d];
    float sn = sinT[s * 32 + d];
    float* p = X + (size_t)row * heads * HD + head * HD + d;
    float a = p[0], b = p[32];
    p[0]  = a * c - b * sn;
    p[32] = b * c + a * sn;
}

// ---------------- Flash attention (fp32, causal, GQA) ----------------
// grid: (S/64, B*H). 128 threads = 4 warps. Each warp: 16 query rows.
// lane = ry*8+cx; thread tile: 4 rows x 8 cols (4 f32x2 pairs).
#define LDQ 65
#define LDK 66
#define LDP 65
#define FLASH_SMEM ((64*LDQ + 64*LDK + 64*64 + 64*LDP) * 4)

__global__ __launch_bounds__(128) void flash_kernel(
    const float* __restrict__ Q,   // [4096,1024]
    const float* __restrict__ K,   // [4096,256] (rope'd, == new_k)
    const float* __restrict__ V,   // [4096,256] (== new_v)
    float* __restrict__ O)         // [4096,1024]
{
    extern __shared__ float sm[];
    float* Qs = sm;                 // [r][d]  64 x LDQ
    float* Ks = Qs + 64 * LDQ;      // [d][c]  64 x LDK (transposed K)
    float* Vs = Ks + 64 * LDK;      // [k][d]  64 x 64
    float* Ps = Vs + 64 * 64;       // [r][k]  64 x LDP

    const int tid  = threadIdx.x;
    const int w    = tid >> 5;
    const int lane = tid & 31;
    const int ry   = lane >> 3;     // 0..3
    const int cx   = lane & 7;      // 0..7
    const int rb   = w * 16 + ry * 4;   // local query-row base (4 rows)
    const int cb   = cx * 8;            // local col base (8 cols)

    const int mt = blockIdx.x;
    const int bh = blockIdx.y;
    const int b  = bh >> 4;
    const int h  = bh & 15;
    const int kv = h >> 2;          // n_rep = 4

    const float* Qg = Q + ((size_t)(b * SEQ + mt * 64)) * DMODEL + h * HD;
    const float* Kg = K + ((size_t)(b * SEQ)) * (NKV * HD) + kv * HD;
    const float* Vg = V + ((size_t)(b * SEQ)) * (NKV * HD) + kv * HD;

    // load Q tile [64 x 64]
#pragma unroll
    for (int i = 0; i < 8; i++) {
        int idx = tid + i * 128;
        int r = idx >> 4;
        int d4 = (idx & 15) * 4;
        float4 t = *(const float4*)(Qg + (size_t)r * DMODEL + d4);
        Qs[r * LDQ + d4 + 0] = t.x;
        Qs[r * LDQ + d4 + 1] = t.y;
        Qs[r * LDQ + d4 + 2] = t.z;
        Qs[r * LDQ + d4 + 3] = t.w;
    }

    ull o2[4][4];
    float m[4], l[4];
#pragma unroll
    for (int i = 0; i < 4; i++) {
        m[i] = -1e30f; l[i] = 0.f;
#pragma unroll
        for (int j = 0; j < 4; j++) o2[i][j] = 0ULL;
    }

    for (int kt = 0; kt <= mt; kt++) {
        __syncthreads();   // prior PV reads (Vs, Ps) done before overwrite
        // load K^T tile and V tile
#pragma unroll
        for (int i = 0; i < 8; i++) {
            int idx = tid + i * 128;
            int c = idx >> 4;
            int d4 = (idx & 15) * 4;
            size_t grow = (size_t)(kt * 64 + c) * (NKV * HD);
            float4 t = *(const float4*)(Kg + grow + d4);
            Ks[(d4 + 0) * LDK + c] = t.x;
            Ks[(d4 + 1) * LDK + c] = t.y;
            Ks[(d4 + 2) * LDK + c] = t.z;
            Ks[(d4 + 3) * LDK + c] = t.w;
            float4 vv = *(const float4*)(Vg + grow + d4);
            *(float4*)&Vs[c * 64 + d4] = vv;
        }
        __syncthreads();

        // S = Q @ K^T  (thread: 4 rows x 4 pairs)
        ull s2[4][4];
#pragma unroll
        for (int i = 0; i < 4; i++)
#pragma unroll
            for (int j = 0; j < 4; j++) s2[i][j] = 0ULL;

#pragma unroll 2
        for (int d = 0; d < 64; d++) {
            ull k2[4];
#pragma unroll
            for (int j = 0; j < 4; j++)
                k2[j] = *(const ull*)&Ks[d * LDK + cb + 2 * j];
#pragma unroll
            for (int i = 0; i < 4; i++) {
                float q = Qs[(rb + i) * LDQ + d];
                ull aa = pack2(q, q);
#pragma unroll
                for (int j = 0; j < 4; j++)
                    s2[i][j] = ffma2(aa, k2[j], s2[i][j]);
            }
        }

        // unpack, scale, causal mask (diagonal tile only)
        float s[4][8];
#pragma unroll
        for (int i = 0; i < 4; i++)
#pragma unroll
            for (int j = 0; j < 4; j++) {
                unpack2(s2[i][j], s[i][2 * j], s[i][2 * j + 1]);
                s[i][2 * j]     *= 0.125f;
                s[i][2 * j + 1] *= 0.125f;
            }
        if (kt == mt) {
#pragma unroll
            for (int i = 0; i < 4; i++)
#pragma unroll
                for (int c = 0; c < 8; c++)
                    if (cb + c > rb + i) s[i][c] = -1e9f;
        }

        // online softmax per row
        float al[4];
#pragma unroll
        for (int i = 0; i < 4; i++) {
            float mx = s[i][0];
#pragma unroll
            for (int c = 1; c < 8; c++) mx = fmaxf(mx, s[i][c]);
            mx = fmaxf(mx, __shfl_xor_sync(0xffffffffu, mx, 1));
            mx = fmaxf(mx, __shfl_xor_sync(0xffffffffu, mx, 2));
            mx = fmaxf(mx, __shfl_xor_sync(0xffffffffu, mx, 4));
            float mnew = fmaxf(m[i], mx);
            float alpha = __expf(m[i] - mnew);
            float sum = 0.f;
#pragma unroll
            for (int c = 0; c < 8; c++) {
                float p = __expf(s[i][c] - mnew);
                s[i][c] = p;
                sum += p;
            }
            sum += __shfl_xor_sync(0xffffffffu, sum, 1);
            sum += __shfl_xor_sync(0xffffffffu, sum, 2);
            sum += __shfl_xor_sync(0xffffffffu, sum, 4);
            l[i] = l[i] * alpha + sum;
            m[i] = mnew;
            al[i] = alpha;
        }

        // write P to smem (scalar stores: exclusive regions)
#pragma unroll
        for (int i = 0; i < 4; i++)
#pragma unroll
            for (int c = 0; c < 8; c++)
                Ps[(rb + i) * LDP + cb + c] = s[i][c];
        __syncthreads();

        // rescale O and accumulate O += P @ V
#pragma unroll
        for (int i = 0; i < 4; i++) {
            ull a2 = pack2(al[i], al[i]);
#pragma unroll
            for (int j = 0; j < 4; j++) o2[i][j] = mul2(o2[i][j], a2);
        }
#pragma unroll 2
        for (int key = 0; key < 64; key++) {
            ull v2[4];
#pragma unroll
            for (int j = 0; j < 4; j++)
                v2[j] = *(const ull*)&Vs[key * 64 + cb + 2 * j];
#pragma unroll
            for (int i = 0; i < 4; i++) {
                float p = Ps[(rb + i) * LDP + key];
                ull pa = pack2(p, p);
#pragma unroll
                for (int j = 0; j < 4; j++)
                    o2[i][j] = ffma2(pa, v2[j], o2[i][j]);
            }
        }
    }

    // epilogue: O /= l, write to g_AO
#pragma unroll
    for (int i = 0; i < 4; i++) {
        float inv = 1.0f / l[i];
        size_t row = (size_t)(b * SEQ + mt * 64 + rb + i);
        float* op = O + row * DMODEL + h * HD + cb;
#pragma unroll
        for (int j = 0; j < 4; j++) {
            float x, y;
            unpack2(o2[i][j], x, y);
            float2 v; v.x = x * inv; v.y = y * inv;
            *(float2*)&op[2 * j] = v;
        }
    }
}

// ---------------- launch ----------------
extern "C" void kernel_launch(void* const* d_in, const int* in_sizes, int n_in,
                              void* d_out, int out_size)
{
    const float* x    = (const float*)d_in[0];
    const float* cosT = (const float*)d_in[1];
    const float* sinT = (const float*)d_in[2];
    // d_in[3] = mask (causal, reproduced analytically)
    const float* wq   = (const float*)d_in[4];
    const float* wk   = (const float*)d_in[5];
    const float* wv   = (const float*)d_in[6];
    const float* wo   = (const float*)d_in[7];

    float* out  = (float*)d_out;                       // [2,2048,1024]
    float* knew = out + (size_t)ROWS * DMODEL;         // [2,2048,4,64]
    float* vnew = knew + (size_t)ROWS * NKV * HD;      // [2,2048,4,64]

    float *Qbuf = nullptr, *AObuf = nullptr;
    cudaGetSymbolAddress((void**)&Qbuf, g_Q);
    cudaGetSymbolAddress((void**)&AObuf, g_AO);
    cudaFuncSetAttribute(flash_kernel, cudaFuncAttributeMaxDynamicSharedMemorySize, FLASH_SMEM);

    // projections
    sgemm_kernel<<<dim3(DMODEL / 128, ROWS / 128), 256>>>(x, wq, Qbuf, ROWS, DMODEL, DMODEL);
    sgemm_kernel<<<dim3((NKV * HD) / 128, ROWS / 128), 256>>>(x, wk, knew, ROWS, NKV * HD, DMODEL);
    sgemm_kernel<<<dim3((NKV * HD) / 128, ROWS / 128), 256>>>(x, wv, vnew, ROWS, NKV * HD, DMODEL);

    // RoPE (in place): Q and new_k
    {
        int totQ = ROWS * NH * 32;
        int totK = ROWS * NKV * 32;
        rope_kernel<<<(totQ + 255) / 256, 256>>>(Qbuf, cosT, sinT, NH, totQ);
        rope_kernel<<<(totK + 255) / 256, 256>>>(knew, cosT, sinT, NKV, totK);
    }

    // attention
    flash_kernel<<<dim3(SEQ / 64, BATCH * NH), 128, FLASH_SMEM>>>(Qbuf, knew, vnew, AObuf);

    // output projection
    sgemm_kernel<<<dim3(DMODEL / 128, ROWS / 128), 256>>>(AObuf, wo, out, ROWS, DMODEL, DMODEL);
}

// round 2
// speedup vs baseline: 1.1142x; 1.1142x over previous
#include <cuda_runtime.h>
#include <cuda_bf16.h>
#include <cstddef>

using ull = unsigned long long;

// ---------------- packed f32x2 helpers (Blackwell FFMA2 path) ----------------
__device__ __forceinline__ ull pack2(float x, float y) {
    ull r; asm("mov.b64 %0, {%1, %2};" : "=l"(r) : "f"(x), "f"(y)); return r;
}
__device__ __forceinline__ void unpack2(ull v, float& x, float& y) {
    asm("mov.b64 {%0, %1}, %2;" : "=f"(x), "=f"(y) : "l"(v));
}
__device__ __forceinline__ ull ffma2(ull a, ull b, ull c) {
    ull d; asm("fma.rn.f32x2 %0, %1, %2, %3;" : "=l"(d) : "l"(a), "l"(b), "l"(c)); return d;
}
__device__ __forceinline__ ull mul2(ull a, ull b) {
    ull d; asm("mul.rn.f32x2 %0, %1, %2;" : "=l"(d) : "l"(a), "l"(b)); return d;
}

// ---------------- problem constants ----------------
#define BATCH 2
#define SEQ   2048
#define DMODEL 1024
#define NH    16
#define NKV   4
#define HD    64
#define ROWS  (BATCH*SEQ)     // 4096

// scratch (device globals; no allocation allowed)
__device__ float g_Q[ROWS * DMODEL];   // Q after projection+rope: [4096,1024]
__device__ float g_AO[ROWS * DMODEL];  // attention output before Wo

// ---------------- GEMM tile body: C[128,128] block of A[M,K]@B[K,N] ----------------
// Double-buffered smem, BK=8, 256 threads, 8x8 per thread, f32x2 accumulators.
#define LDA_S 132
#define AS_STRIDE (8 * LDA_S)
#define BS_STRIDE (8 * 128)

__device__ __forceinline__ void gemm_body(
    const float* __restrict__ A, const float* __restrict__ B, float* __restrict__ C,
    int N, int K, int brow, int bcol, float* As, float* Bs)
{
    const int tid  = threadIdx.x;
    const int ty = tid >> 4;          // 0..15 -> row group
    const int tx = tid & 15;          // 0..15 -> col group

    const int arow = tid >> 1;        // 0..127
    const int acol = (tid & 1) * 4;   // 0 or 4
    const int brw  = tid >> 5;        // 0..7
    const int bcl  = (tid & 31) * 4;  // 0..124

    const float* Ap = A + (size_t)(brow + arow) * K + acol;
    const float* Bp = B + (size_t)brw * N + bcol + bcl;

    ull acc[8][4];
#pragma unroll
    for (int i = 0; i < 8; i++)
#pragma unroll
        for (int j = 0; j < 4; j++) acc[i][j] = 0ULL;

    // preload first tile into buffer 0
    float4 a = *(const float4*)Ap;
    float4 b4 = *(const float4*)Bp;
    As[(acol + 0) * LDA_S + arow] = a.x;
    As[(acol + 1) * LDA_S + arow] = a.y;
    As[(acol + 2) * LDA_S + arow] = a.z;
    As[(acol + 3) * LDA_S + arow] = a.w;
    *(float4*)&Bs[brw * 128 + bcl] = b4;
    __syncthreads();

    int buf = 0;
    for (int k0 = 0; k0 < K; k0 += 8) {
        const bool has_next = (k0 + 8 < K);
        if (has_next) {
            a  = *(const float4*)(Ap + k0 + 8);
            b4 = *(const float4*)(Bp + (size_t)(k0 + 8) * N);
        }
        const float* Asc = As + buf * AS_STRIDE;
        const float* Bsc = Bs + buf * BS_STRIDE;

#pragma unroll
        for (int kk = 0; kk < 8; kk++) {
            float4 a0 = *(const float4*)&Asc[kk * LDA_S + ty * 8];
            float4 a1 = *(const float4*)&Asc[kk * LDA_S + ty * 8 + 4];
            const ull* bp = (const ull*)&Bsc[kk * 128 + tx * 8];
            ull b0 = bp[0], b1 = bp[1], b2 = bp[2], b3 = bp[3];
            float av[8] = {a0.x, a0.y, a0.z, a0.w, a1.x, a1.y, a1.z, a1.w};
#pragma unroll
            for (int i = 0; i < 8; i++) {
                ull aa = pack2(av[i], av[i]);
                acc[i][0] = ffma2(aa, b0, acc[i][0]);
                acc[i][1] = ffma2(aa, b1, acc[i][1]);
                acc[i][2] = ffma2(aa, b2, acc[i][2]);
                acc[i][3] = ffma2(aa, b3, acc[i][3]);
            }
        }

        if (has_next) {
            float* Asn = As + (buf ^ 1) * AS_STRIDE;
            float* Bsn = Bs + (buf ^ 1) * BS_STRIDE;
            Asn[(acol + 0) * LDA_S + arow] = a.x;
            Asn[(acol + 1) * LDA_S + arow] = a.y;
            Asn[(acol + 2) * LDA_S + arow] = a.z;
            Asn[(acol + 3) * LDA_S + arow] = a.w;
            *(float4*)&Bsn[brw * 128 + bcl] = b4;
        }
        __syncthreads();
        buf ^= 1;
    }

#pragma unroll
    for (int i = 0; i < 8; i++) {
        float* crow = C + (size_t)(brow + ty * 8 + i) * N + bcol + tx * 8;
#pragma unroll
        for (int j = 0; j < 4; j++) {
            *(ull*)&crow[2 * j] = acc[i][j];
        }
    }
}

// ---------------- fused QKV projection ----------------
// grid.x: 0..7 -> Q cols, 8..9 -> K cols, 10..11 -> V cols.  grid.y: row tiles.
__global__ __launch_bounds__(256) void qkv_kernel(
    const float* __restrict__ x,
    const float* __restrict__ wq, const float* __restrict__ wk, const float* __restrict__ wv,
    float* __restrict__ Qb, float* __restrict__ Kb, float* __restrict__ Vb)
{
    __shared__ float As[2 * AS_STRIDE];
    __shared__ float Bs[2 * BS_STRIDE];
    const int bx = blockIdx.x;
    const int brow = blockIdx.y * 128;
    if (bx < 8) {
        gemm_body(x, wq, Qb, DMODEL, DMODEL, brow, bx * 128, As, Bs);
    } else if (bx < 10) {
        gemm_body(x, wk, Kb, NKV * HD, DMODEL, brow, (bx - 8) * 128, As, Bs);
    } else {
        gemm_body(x, wv, Vb, NKV * HD, DMODEL, brow, (bx - 10) * 128, As, Bs);
    }
}

__global__ __launch_bounds__(256) void wo_kernel(
    const float* __restrict__ A, const float* __restrict__ B, float* __restrict__ C)
{
    __shared__ float As[2 * AS_STRIDE];
    __shared__ float Bs[2 * BS_STRIDE];
    gemm_body(A, B, C, DMODEL, DMODEL, blockIdx.y * 128, blockIdx.x * 128, As, Bs);
}

// ---------------- RoPE (in place) ----------------
__global__ void rope_kernel(float* __restrict__ X,
                            const float* __restrict__ cosT,
                            const float* __restrict__ sinT,
                            int heads, int total)
{
    int idx = blockIdx.x * blockDim.x + threadIdx.x;
    if (idx >= total) return;
    int d    = idx & 31;
    int rest = idx >> 5;
    int head = rest % heads;
    int row  = rest / heads;
    int s    = row & (SEQ - 1);
    float c  = cosT[s * 32 + d];
    float sn = sinT[s * 32 + d];
    float* p = X + (size_t)row * heads * HD + head * HD + d;
    float a = p[0], b = p[32];
    p[0]  = a * c - b * sn;
    p[32] = b * c + a * sn;
}

// ---------------- Flash attention v2 (fp32, causal, GQA) ----------------
// 128-query x 64-key tiles, 256 threads = 8 warps. Thread tile 4 rows x 8 cols.
#define LDQ 65
#define LDK 66
#define LDP 65
#define QROWS 128
#define FLASH_SMEM ((QROWS*LDQ + 64*LDK + 64*64 + QROWS*LDP) * 4)

__global__ __launch_bounds__(256, 2) void flash_kernel(
    const float* __restrict__ Q,   // [4096,1024]
    const float* __restrict__ K,   // [4096,256] (rope'd, == new_k)
    const float* __restrict__ V,   // [4096,256] (== new_v)
    float* __restrict__ O)         // [4096,1024]
{
    extern __shared__ float sm[];
    float* Qs = sm;                      // [r][d]  128 x LDQ
    float* Ks = Qs + QROWS * LDQ;        // [d][c]  64 x LDK (transposed K)
    float* Vs = Ks + 64 * LDK;           // [k][d]  64 x 64
    float* Ps = Vs + 64 * 64;            // [r][k]  128 x LDP

    const int tid  = threadIdx.x;
    const int w    = tid >> 5;
    const int lane = tid & 31;
    const int ry   = lane >> 3;
    const int cx   = lane & 7;
    const int rb   = w * 16 + ry * 4;    // local query-row base (4 rows)
    const int cb   = cx * 8;             // local col base (8 cols)

    const int mt = gridDim.x - 1 - blockIdx.x;   // heavy blocks first
    const int bh = blockIdx.y;
    const int b  = bh >> 4;
    const int h  = bh & 15;
    const int kv = h >> 2;

    const float* Qg = Q + ((size_t)(b * SEQ + mt * QROWS)) * DMODEL + h * HD;
    const float* Kg = K + ((size_t)(b * SEQ)) * (NKV * HD) + kv * HD;
    const float* Vg = V + ((size_t)(b * SEQ)) * (NKV * HD) + kv * HD;

    // load Q tile [128 x 64]
#pragma unroll
    for (int i = 0; i < 8; i++) {
        int idx = tid + i * 256;
        int r = idx >> 4;
        int d4 = (idx & 15) * 4;
        float4 t = *(const float4*)(Qg + (size_t)r * DMODEL + d4);
        Qs[r * LDQ + d4 + 0] = t.x;
        Qs[r * LDQ + d4 + 1] = t.y;
        Qs[r * LDQ + d4 + 2] = t.z;
        Qs[r * LDQ + d4 + 3] = t.w;
    }

    ull o2[4][4];
    float m[4], l[4];
#pragma unroll
    for (int i = 0; i < 4; i++) {
        m[i] = -1e30f; l[i] = 0.f;
#pragma unroll
        for (int j = 0; j < 4; j++) o2[i][j] = 0ULL;
    }

    const int ktmax = 2 * mt + 1;
    for (int kt = 0; kt <= ktmax; kt++) {
        __syncthreads();   // prior PV reads done before overwrite
        // load K^T tile and V tile [64 x 64]
#pragma unroll
        for (int i = 0; i < 4; i++) {
            int idx = tid + i * 256;
            int c = idx >> 4;
            int d4 = (idx & 15) * 4;
            size_t grow = (size_t)(kt * 64 + c) * (NKV * HD);
            float4 t = *(const float4*)(Kg + grow + d4);
            Ks[(d4 + 0) * LDK + c] = t.x;
            Ks[(d4 + 1) * LDK + c] = t.y;
            Ks[(d4 + 2) * LDK + c] = t.z;
            Ks[(d4 + 3) * LDK + c] = t.w;
            float4 vv = *(const float4*)(Vg + grow + d4);
            *(float4*)&Vs[c * 64 + d4] = vv;
        }
        __syncthreads();

        // last diagonal tile: rows entirely above the key range are fully masked
        const bool skip = (kt == ktmax) && (rb + 3 < 64);
        float al[4];

        if (!skip) {
            // S = Q @ K^T
            ull s2[4][4];
#pragma unroll
            for (int i = 0; i < 4; i++)
#pragma unroll
                for (int j = 0; j < 4; j++) s2[i][j] = 0ULL;

#pragma unroll 2
            for (int d = 0; d < 64; d++) {
                ull k2[4];
#pragma unroll
                for (int j = 0; j < 4; j++)
                    k2[j] = *(const ull*)&Ks[d * LDK + cb + 2 * j];
#pragma unroll
                for (int i = 0; i < 4; i++) {
                    float q = Qs[(rb + i) * LDQ + d];
                    ull aa = pack2(q, q);
#pragma unroll
                    for (int j = 0; j < 4; j++)
                        s2[i][j] = ffma2(aa, k2[j], s2[i][j]);
                }
            }

            float s[4][8];
#pragma unroll
            for (int i = 0; i < 4; i++)
#pragma unroll
                for (int j = 0; j < 4; j++) {
                    unpack2(s2[i][j], s[i][2 * j], s[i][2 * j + 1]);
                    s[i][2 * j]     *= 0.125f;
                    s[i][2 * j + 1] *= 0.125f;
                }
            if (kt >= 2 * mt) {   // partially masked tiles
#pragma unroll
                for (int i = 0; i < 4; i++) {
                    int rglob = mt * QROWS + rb + i;
#pragma unroll
                    for (int c = 0; c < 8; c++)
                        if (kt * 64 + cb + c > rglob) s[i][c] = -1e9f;
                }
            }

            // online softmax per row
#pragma unroll
            for (int i = 0; i < 4; i++) {
                float mx = s[i][0];
#pragma unroll
                for (int c = 1; c < 8; c++) mx = fmaxf(mx, s[i][c]);
                mx = fmaxf(mx, __shfl_xor_sync(0xffffffffu, mx, 1));
                mx = fmaxf(mx, __shfl_xor_sync(0xffffffffu, mx, 2));
                mx = fmaxf(mx, __shfl_xor_sync(0xffffffffu, mx, 4));
                float mnew = fmaxf(m[i], mx);
                float alpha = __expf(m[i] - mnew);
                float sum = 0.f;
#pragma unroll
                for (int c = 0; c < 8; c++) {
                    float p = __expf(s[i][c] - mnew);
                    s[i][c] = p;
                    sum += p;
                }
                sum += __shfl_xor_sync(0xffffffffu, sum, 1);
                sum += __shfl_xor_sync(0xffffffffu, sum, 2);
                sum += __shfl_xor_sync(0xffffffffu, sum, 4);
                l[i] = l[i] * alpha + sum;
                m[i] = mnew;
                al[i] = alpha;
            }

            // write P to smem (exclusive regions)
#pragma unroll
            for (int i = 0; i < 4; i++)
#pragma unroll
                for (int c = 0; c < 8; c++)
                    Ps[(rb + i) * LDP + cb + c] = s[i][c];
        }
        __syncthreads();

        if (!skip) {
            // rescale O and accumulate O += P @ V
#pragma unroll
            for (int i = 0; i < 4; i++) {
                ull a2 = pack2(al[i], al[i]);
#pragma unroll
                for (int j = 0; j < 4; j++) o2[i][j] = mul2(o2[i][j], a2);
            }
#pragma unroll 2
            for (int key = 0; key < 64; key++) {
                ull v2[4];
#pragma unroll
                for (int j = 0; j < 4; j++)
                    v2[j] = *(const ull*)&Vs[key * 64 + cb + 2 * j];
#pragma unroll
                for (int i = 0; i < 4; i++) {
                    float p = Ps[(rb + i) * LDP + key];
                    ull pa = pack2(p, p);
#pragma unroll
                    for (int j = 0; j < 4; j++)
                        o2[i][j] = ffma2(pa, v2[j], o2[i][j]);
                }
            }
        }
    }

    // epilogue: O /= l
#pragma unroll
    for (int i = 0; i < 4; i++) {
        float inv = 1.0f / l[i];
        size_t row = (size_t)(b * SEQ + mt * QROWS + rb + i);
        float* op = O + row * DMODEL + h * HD + cb;
#pragma unroll
        for (int j = 0; j < 4; j++) {
            float x, y;
            unpack2(o2[i][j], x, y);
            float2 v; v.x = x * inv; v.y = y * inv;
            *(float2*)&op[2 * j] = v;
        }
    }
}

// ---------------- launch ----------------
extern "C" void kernel_launch(void* const* d_in, const int* in_sizes, int n_in,
                              void* d_out, int out_size)
{
    const float* x    = (const float*)d_in[0];
    const float* cosT = (const float*)d_in[1];
    const float* sinT = (const float*)d_in[2];
    // d_in[3] = mask (causal, reproduced analytically)
    const float* wq   = (const float*)d_in[4];
    const float* wk   = (const float*)d_in[5];
    const float* wv   = (const float*)d_in[6];
    const float* wo   = (const float*)d_in[7];

    float* out  = (float*)d_out;                       // [2,2048,1024]
    float* knew = out + (size_t)ROWS * DMODEL;         // [2,2048,4,64]
    float* vnew = knew + (size_t)ROWS * NKV * HD;      // [2,2048,4,64]

    float *Qbuf = nullptr, *AObuf = nullptr;
    cudaGetSymbolAddress((void**)&Qbuf, g_Q);
    cudaGetSymbolAddress((void**)&AObuf, g_AO);
    cudaFuncSetAttribute(flash_kernel, cudaFuncAttributeMaxDynamicSharedMemorySize, FLASH_SMEM);

    // fused QKV projections (one launch, 384 blocks)
    qkv_kernel<<<dim3(12, ROWS / 128), 256>>>(x, wq, wk, wv, Qbuf, knew, vnew);

    // RoPE (in place): Q and new_k
    {
        int totQ = ROWS * NH * 32;
        int totK = ROWS * NKV * 32;
        rope_kernel<<<(totQ + 255) / 256, 256>>>(Qbuf, cosT, sinT, NH, totQ);
        rope_kernel<<<(totK + 255) / 256, 256>>>(knew, cosT, sinT, NKV, totK);
    }

    // attention
    flash_kernel<<<dim3(SEQ / QROWS, BATCH * NH), 256, FLASH_SMEM>>>(Qbuf, knew, vnew, AObuf);

    // output projection
    wo_kernel<<<dim3(DMODEL / 128, ROWS / 128), 256>>>(AObuf, wo, out);
}

// round 3
// speedup vs baseline: 1.1150x; 1.0007x over previous
#include <cuda_runtime.h>
#include <cuda_bf16.h>
#include <cstddef>

using ull = unsigned long long;

// ---------------- packed f32x2 helpers (Blackwell FFMA2 path) ----------------
__device__ __forceinline__ ull pack2(float x, float y) {
    ull r; asm("mov.b64 %0, {%1, %2};" : "=l"(r) : "f"(x), "f"(y)); return r;
}
__device__ __forceinline__ void unpack2(ull v, float& x, float& y) {
    asm("mov.b64 {%0, %1}, %2;" : "=f"(x), "=f"(y) : "l"(v));
}
__device__ __forceinline__ ull ffma2(ull a, ull b, ull c) {
    ull d; asm("fma.rn.f32x2 %0, %1, %2, %3;" : "=l"(d) : "l"(a), "l"(b), "l"(c)); return d;
}
__device__ __forceinline__ ull mul2(ull a, ull b) {
    ull d; asm("mul.rn.f32x2 %0, %1, %2;" : "=l"(d) : "l"(a), "l"(b)); return d;
}

// ---------------- problem constants ----------------
#define BATCH 2
#define SEQ   2048
#define DMODEL 1024
#define NH    16
#define NKV   4
#define HD    64
#define ROWS  (BATCH*SEQ)     // 4096

// scratch (device globals; no allocation allowed)
__device__ float g_Q[ROWS * DMODEL];            // Q after projection+rope
__device__ float g_AO[ROWS * DMODEL];           // attention output before Wo
__device__ float g_KT[BATCH * NKV * HD * SEQ];  // K^T: [b][kv][d][s]

// ---------------- GEMM tile body (unchanged from R2) ----------------
#define LDA_S 132
#define AS_STRIDE (8 * LDA_S)
#define BS_STRIDE (8 * 128)

__device__ __forceinline__ void gemm_body(
    const float* __restrict__ A, const float* __restrict__ B, float* __restrict__ C,
    int N, int K, int brow, int bcol, float* As, float* Bs)
{
    const int tid  = threadIdx.x;
    const int ty = tid >> 4;
    const int tx = tid & 15;

    const int arow = tid >> 1;
    const int acol = (tid & 1) * 4;
    const int brw  = tid >> 5;
    const int bcl  = (tid & 31) * 4;

    const float* Ap = A + (size_t)(brow + arow) * K + acol;
    const float* Bp = B + (size_t)brw * N + bcol + bcl;

    ull acc[8][4];
#pragma unroll
    for (int i = 0; i < 8; i++)
#pragma unroll
        for (int j = 0; j < 4; j++) acc[i][j] = 0ULL;

    float4 a = *(const float4*)Ap;
    float4 b4 = *(const float4*)Bp;
    As[(acol + 0) * LDA_S + arow] = a.x;
    As[(acol + 1) * LDA_S + arow] = a.y;
    As[(acol + 2) * LDA_S + arow] = a.z;
    As[(acol + 3) * LDA_S + arow] = a.w;
    *(float4*)&Bs[brw * 128 + bcl] = b4;
    __syncthreads();

    int buf = 0;
    for (int k0 = 0; k0 < K; k0 += 8) {
        const bool has_next = (k0 + 8 < K);
        if (has_next) {
            a  = *(const float4*)(Ap + k0 + 8);
            b4 = *(const float4*)(Bp + (size_t)(k0 + 8) * N);
        }
        const float* Asc = As + buf * AS_STRIDE;
        const float* Bsc = Bs + buf * BS_STRIDE;

#pragma unroll
        for (int kk = 0; kk < 8; kk++) {
            float4 a0 = *(const float4*)&Asc[kk * LDA_S + ty * 8];
            float4 a1 = *(const float4*)&Asc[kk * LDA_S + ty * 8 + 4];
            const ull* bp = (const ull*)&Bsc[kk * 128 + tx * 8];
            ull b0 = bp[0], b1 = bp[1], b2 = bp[2], b3 = bp[3];
            float av[8] = {a0.x, a0.y, a0.z, a0.w, a1.x, a1.y, a1.z, a1.w};
#pragma unroll
            for (int i = 0; i < 8; i++) {
                ull aa = pack2(av[i], av[i]);
                acc[i][0] = ffma2(aa, b0, acc[i][0]);
                acc[i][1] = ffma2(aa, b1, acc[i][1]);
                acc[i][2] = ffma2(aa, b2, acc[i][2]);
                acc[i][3] = ffma2(aa, b3, acc[i][3]);
            }
        }

        if (has_next) {
            float* Asn = As + (buf ^ 1) * AS_STRIDE;
            float* Bsn = Bs + (buf ^ 1) * BS_STRIDE;
            Asn[(acol + 0) * LDA_S + arow] = a.x;
            Asn[(acol + 1) * LDA_S + arow] = a.y;
            Asn[(acol + 2) * LDA_S + arow] = a.z;
            Asn[(acol + 3) * LDA_S + arow] = a.w;
            *(float4*)&Bsn[brw * 128 + bcl] = b4;
        }
        __syncthreads();
        buf ^= 1;
    }

#pragma unroll
    for (int i = 0; i < 8; i++) {
        float* crow = C + (size_t)(brow + ty * 8 + i) * N + bcol + tx * 8;
#pragma unroll
        for (int j = 0; j < 4; j++) {
            *(ull*)&crow[2 * j] = acc[i][j];
        }
    }
}

__global__ __launch_bounds__(256) void qkv_kernel(
    const float* __restrict__ x,
    const float* __restrict__ wq, const float* __restrict__ wk, const float* __restrict__ wv,
    float* __restrict__ Qb, float* __restrict__ Kb, float* __restrict__ Vb)
{
    __shared__ float As[2 * AS_STRIDE];
    __shared__ float Bs[2 * BS_STRIDE];
    const int bx = blockIdx.x;
    const int brow = blockIdx.y * 128;
    if (bx < 8) {
        gemm_body(x, wq, Qb, DMODEL, DMODEL, brow, bx * 128, As, Bs);
    } else if (bx < 10) {
        gemm_body(x, wk, Kb, NKV * HD, DMODEL, brow, (bx - 8) * 128, As, Bs);
    } else {
        gemm_body(x, wv, Vb, NKV * HD, DMODEL, brow, (bx - 10) * 128, As, Bs);
    }
}

__global__ __launch_bounds__(256) void wo_kernel(
    const float* __restrict__ A, const float* __restrict__ B, float* __restrict__ C)
{
    __shared__ float As[2 * AS_STRIDE];
    __shared__ float Bs[2 * BS_STRIDE];
    gemm_body(A, B, C, DMODEL, DMODEL, blockIdx.y * 128, blockIdx.x * 128, As, Bs);
}

// ---------------- RoPE Q (in place) ----------------
__global__ void rope_q_kernel(float* __restrict__ X,
                              const float* __restrict__ cosT,
                              const float* __restrict__ sinT)
{
    int idx = blockIdx.x * blockDim.x + threadIdx.x;   // ROWS*NH*32 threads
    int d    = idx & 31;
    int rest = idx >> 5;
    int head = rest & (NH - 1);
    int row  = rest >> 4;
    int s    = row & (SEQ - 1);
    float c  = cosT[s * 32 + d];
    float sn = sinT[s * 32 + d];
    float* p = X + (size_t)row * NH * HD + head * HD + d;
    float a = p[0], b = p[32];
    p[0]  = a * c - b * sn;
    p[32] = b * c + a * sn;
}

// ---------------- RoPE K (in place) + transposed copy KT[b][kv][d][s] ----------------
__global__ void rope_k_kernel(float* __restrict__ X,
                              float* __restrict__ KT,
                              const float* __restrict__ cosT,
                              const float* __restrict__ sinT)
{
    int idx = blockIdx.x * blockDim.x + threadIdx.x;   // ROWS*NKV*32 threads
    int d    = idx & 31;
    int rest = idx >> 5;
    int head = rest & (NKV - 1);
    int row  = rest >> 2;
    int s    = row & (SEQ - 1);
    int b    = row >> 11;
    float c  = cosT[s * 32 + d];
    float sn = sinT[s * 32 + d];
    float* p = X + (size_t)row * NKV * HD + head * HD + d;
    float a = p[0], bb = p[32];
    float na = a * c - bb * sn;
    float nb = bb * c + a * sn;
    p[0]  = na;
    p[32] = nb;
    float* kt = KT + ((size_t)(b * NKV + head) * HD) * SEQ;
    kt[(size_t)d * SEQ + s]        = na;
    kt[(size_t)(d + 32) * SEQ + s] = nb;
}

// ---------------- Flash attention v3 (fp32, causal, GQA) ----------------
// 128-query x 64-key tiles, 256 threads = 8 warps. Thread tile 4 rows x 8 cols.
// All smem traffic LDS.128 / STS.128. K comes pre-transposed from g_KT.
#define LDQ 68
#define LDK 68
#define LDP 68
#define QROWS 128
#define FLASH_SMEM ((QROWS*LDQ + 64*LDK + 64*64 + QROWS*LDP) * 4)

__global__ __launch_bounds__(256, 2) void flash_kernel(
    const float* __restrict__ Q,    // [4096,1024] (rope'd, pre-scaled here)
    const float* __restrict__ KT,   // [b][kv][64][2048]
    const float* __restrict__ V,    // [4096,256]
    float* __restrict__ O)
{
    extern __shared__ float sm[];
    float* Qs = sm;                      // [r][d]  128 x LDQ
    float* Ks = Qs + QROWS * LDQ;        // [d][c]  64 x LDK
    float* Vs = Ks + 64 * LDK;           // [k][d]  64 x 64
    float* Ps = Vs + 64 * 64;            // [r][k]  128 x LDP

    const int tid  = threadIdx.x;
    const int w    = tid >> 5;
    const int lane = tid & 31;
    const int ry   = lane >> 3;
    const int cx   = lane & 7;
    const int rb   = w * 16 + ry * 4;
    const int cb   = cx * 8;

    const int mt = gridDim.x - 1 - blockIdx.x;   // heavy blocks first
    const int bh = blockIdx.y;
    const int b  = bh >> 4;
    const int h  = bh & 15;
    const int kv = h >> 2;

    const float* Qg  = Q + ((size_t)(b * SEQ + mt * QROWS)) * DMODEL + h * HD;
    const float* KTg = KT + ((size_t)(b * NKV + kv) * HD) * SEQ;
    const float* Vg  = V + ((size_t)(b * SEQ)) * (NKV * HD) + kv * HD;

    // load Q tile [128 x 64], fold in 1/sqrt(HD) = 0.125
#pragma unroll
    for (int i = 0; i < 8; i++) {
        int idx = tid + i * 256;
        int r = idx >> 4;
        int d4 = (idx & 15) * 4;
        float4 t = *(const float4*)(Qg + (size_t)r * DMODEL + d4);
        t.x *= 0.125f; t.y *= 0.125f; t.z *= 0.125f; t.w *= 0.125f;
        *(float4*)&Qs[r * LDQ + d4] = t;
    }

    ull o2[4][4];
    float m[4], l[4];
#pragma unroll
    for (int i = 0; i < 4; i++) {
        m[i] = -1e30f; l[i] = 0.f;
#pragma unroll
        for (int j = 0; j < 4; j++) o2[i][j] = 0ULL;
    }

    const int ktmax = 2 * mt + 1;
    for (int kt = 0; kt <= ktmax; kt++) {
        __syncthreads();   // prior PV reads done before overwrite
        // load K^T tile [64 d x 64 c] (coalesced rows of KT) and V tile [64 x 64]
#pragma unroll
        for (int i = 0; i < 4; i++) {
            int idx = tid + i * 256;
            int r  = idx >> 4;           // d for K, key for V
            int c4 = (idx & 15) * 4;
            float4 t = *(const float4*)(KTg + (size_t)r * SEQ + kt * 64 + c4);
            *(float4*)&Ks[r * LDK + c4] = t;
            float4 vv = *(const float4*)(Vg + (size_t)(kt * 64 + r) * (NKV * HD) + c4);
            *(float4*)&Vs[r * 64 + c4] = vv;
        }
        __syncthreads();

        const bool skip = (kt == ktmax) && (rb + 3 < 64);
        float al[4];

        if (!skip) {
            // S = Q @ K^T
            ull s2[4][4];
#pragma unroll
            for (int i = 0; i < 4; i++)
#pragma unroll
                for (int j = 0; j < 4; j++) s2[i][j] = 0ULL;

#pragma unroll 2
            for (int d0 = 0; d0 < 64; d0 += 4) {
                float4 q4[4];
#pragma unroll
                for (int i = 0; i < 4; i++)
                    q4[i] = *(const float4*)&Qs[(rb + i) * LDQ + d0];
#pragma unroll
                for (int dd = 0; dd < 4; dd++) {
                    const float* krow = &Ks[(d0 + dd) * LDK + cb];
                    ulonglong2 kA = *(const ulonglong2*)krow;
                    ulonglong2 kB = *(const ulonglong2*)(krow + 4);
#pragma unroll
                    for (int i = 0; i < 4; i++) {
                        float qv = (dd == 0) ? q4[i].x : (dd == 1) ? q4[i].y
                                 : (dd == 2) ? q4[i].z : q4[i].w;
                        ull aa = pack2(qv, qv);
                        s2[i][0] = ffma2(aa, kA.x, s2[i][0]);
                        s2[i][1] = ffma2(aa, kA.y, s2[i][1]);
                        s2[i][2] = ffma2(aa, kB.x, s2[i][2]);
                        s2[i][3] = ffma2(aa, kB.y, s2[i][3]);
                    }
                }
            }

            float s[4][8];
#pragma unroll
            for (int i = 0; i < 4; i++)
#pragma unroll
                for (int j = 0; j < 4; j++)
                    unpack2(s2[i][j], s[i][2 * j], s[i][2 * j + 1]);

            if (kt >= 2 * mt) {   // partially masked tiles
#pragma unroll
                for (int i = 0; i < 4; i++) {
                    int rglob = mt * QROWS + rb + i;
#pragma unroll
                    for (int c = 0; c < 8; c++)
                        if (kt * 64 + cb + c > rglob) s[i][c] = -1e9f;
                }
            }

            // online softmax per row
#pragma unroll
            for (int i = 0; i < 4; i++) {
                float mx = s[i][0];
#pragma unroll
                for (int c = 1; c < 8; c++) mx = fmaxf(mx, s[i][c]);
                mx = fmaxf(mx, __shfl_xor_sync(0xffffffffu, mx, 1));
                mx = fmaxf(mx, __shfl_xor_sync(0xffffffffu, mx, 2));
                mx = fmaxf(mx, __shfl_xor_sync(0xffffffffu, mx, 4));
                float mnew = fmaxf(m[i], mx);
                float alpha = __expf(m[i] - mnew);
                float sum = 0.f;
#pragma unroll
                for (int c = 0; c < 8; c++) {
                    float p = __expf(s[i][c] - mnew);
                    s[i][c] = p;
                    sum += p;
                }
                sum += __shfl_xor_sync(0xffffffffu, sum, 1);
                sum += __shfl_xor_sync(0xffffffffu, sum, 2);
                sum += __shfl_xor_sync(0xffffffffu, sum, 4);
                l[i] = l[i] * alpha + sum;
                m[i] = mnew;
                al[i] = alpha;
            }

            // write P to smem (STS.128 x2 per row)
#pragma unroll
            for (int i = 0; i < 4; i++) {
                float* pr = &Ps[(rb + i) * LDP + cb];
                *(float4*)pr       = make_float4(s[i][0], s[i][1], s[i][2], s[i][3]);
                *(float4*)(pr + 4) = make_float4(s[i][4], s[i][5], s[i][6], s[i][7]);
            }
        }
        __syncthreads();

        if (!skip) {
            // rescale O, accumulate O += P @ V
#pragma unroll
            for (int i = 0; i < 4; i++) {
                ull a2 = pack2(al[i], al[i]);
#pragma unroll
                for (int j = 0; j < 4; j++) o2[i][j] = mul2(o2[i][j], a2);
            }
#pragma unroll 2
            for (int k0 = 0; k0 < 64; k0 += 4) {
                float4 p4[4];
#pragma unroll
                for (int i = 0; i < 4; i++)
                    p4[i] = *(const float4*)&Ps[(rb + i) * LDP + k0];
#pragma unroll
                for (int kk = 0; kk < 4; kk++) {
                    const float* vrow = &Vs[(k0 + kk) * 64 + cb];
                    ulonglong2 vA = *(const ulonglong2*)vrow;
                    ulonglong2 vB = *(const ulonglong2*)(vrow + 4);
#pragma unroll
                    for (int i = 0; i < 4; i++) {
                        float pv = (kk == 0) ? p4[i].x : (kk == 1) ? p4[i].y
                                 : (kk == 2) ? p4[i].z : p4[i].w;
                        ull pa = pack2(pv, pv);
                        o2[i][0] = ffma2(pa, vA.x, o2[i][0]);
                        o2[i][1] = ffma2(pa, vA.y, o2[i][1]);
                        o2[i][2] = ffma2(pa, vB.x, o2[i][2]);
                        o2[i][3] = ffma2(pa, vB.y, o2[i][3]);
                    }
                }
            }
        }
    }

    // epilogue: O /= l
#pragma unroll
    for (int i = 0; i < 4; i++) {
        float inv = 1.0f / l[i];
        size_t row = (size_t)(b * SEQ + mt * QROWS + rb + i);
        float* op = O + row * DMODEL + h * HD + cb;
#pragma unroll
        for (int j = 0; j < 4; j++) {
            float x, y;
            unpack2(o2[i][j], x, y);
            float2 v; v.x = x * inv; v.y = y * inv;
            *(float2*)&op[2 * j] = v;
        }
    }
}

// ---------------- launch ----------------
extern "C" void kernel_launch(void* const* d_in, const int* in_sizes, int n_in,
                              void* d_out, int out_size)
{
    const float* x    = (const float*)d_in[0];
    const float* cosT = (const float*)d_in[1];
    const float* sinT = (const float*)d_in[2];
    // d_in[3] = mask (causal, reproduced analytically)
    const float* wq   = (const float*)d_in[4];
    const float* wk   = (const float*)d_in[5];
    const float* wv   = (const float*)d_in[6];
    const float* wo   = (const float*)d_in[7];

    float* out  = (float*)d_out;                       // [2,2048,1024]
    float* knew = out + (size_t)ROWS * DMODEL;         // [2,2048,4,64]
    float* vnew = knew + (size_t)ROWS * NKV * HD;      // [2,2048,4,64]

    float *Qbuf = nullptr, *AObuf = nullptr, *KTbuf = nullptr;
    cudaGetSymbolAddress((void**)&Qbuf, g_Q);
    cudaGetSymbolAddress((void**)&AObuf, g_AO);
    cudaGetSymbolAddress((void**)&KTbuf, g_KT);
    cudaFuncSetAttribute(flash_kernel, cudaFuncAttributeMaxDynamicSharedMemorySize, FLASH_SMEM);

    // fused QKV projections (one launch, 384 blocks)
    qkv_kernel<<<dim3(12, ROWS / 128), 256>>>(x, wq, wk, wv, Qbuf, knew, vnew);

    // RoPE: Q in place; K in place + transposed copy
    rope_q_kernel<<<(ROWS * NH * 32) / 256, 256>>>(Qbuf, cosT, sinT);
    rope_k_kernel<<<(ROWS * NKV * 32) / 256, 256>>>(knew, KTbuf, cosT, sinT);

    // attention
    flash_kernel<<<dim3(SEQ / QROWS, BATCH * NH), 256, FLASH_SMEM>>>(Qbuf, KTbuf, vnew, AObuf);

    // output projection
    wo_kernel<<<dim3(DMODEL / 128, ROWS / 128), 256>>>(AObuf, wo, out);
}

// round 4
// speedup vs baseline: 1.5592x; 1.3984x over previous
#include <cuda_runtime.h>
#include <cuda_bf16.h>
#include <cstddef>

using ull = unsigned long long;

// ---------------- packed f32x2 helpers (Blackwell FFMA2 path) ----------------
__device__ __forceinline__ ull pack2(float x, float y) {
    ull r; asm("mov.b64 %0, {%1, %2};" : "=l"(r) : "f"(x), "f"(y)); return r;
}
__device__ __forceinline__ void unpack2(ull v, float& x, float& y) {
    asm("mov.b64 {%0, %1}, %2;" : "=f"(x), "=f"(y) : "l"(v));
}
__device__ __forceinline__ ull ffma2(ull a, ull b, ull c) {
    ull d; asm("fma.rn.f32x2 %0, %1, %2, %3;" : "=l"(d) : "l"(a), "l"(b), "l"(c)); return d;
}
__device__ __forceinline__ ull mul2(ull a, ull b) {
    ull d; asm("mul.rn.f32x2 %0, %1, %2;" : "=l"(d) : "l"(a), "l"(b)); return d;
}

// ---------------- problem constants ----------------
#define BATCH 2
#define SEQ   2048
#define DMODEL 1024
#define NH    16
#define NKV   4
#define HD    64
#define ROWS  (BATCH*SEQ)     // 4096

__device__ float g_Q[ROWS * DMODEL];            // Q after projection+rope (pre-scaled in flash)
__device__ float g_AO[ROWS * DMODEL];           // attention output before Wo
__device__ float g_KT[BATCH * NKV * HD * SEQ];  // K^T: [b][kv][d][s]

// ---------------- GEMM tile body ----------------
// BM=BN=128, BK=8, 256 threads, 8x8/thread, split-column mapping (tx*4 | 64+tx*4).
#define LDA_S 132
#define AS_STRIDE (8 * LDA_S)
#define BS_STRIDE (8 * 128)

__device__ __forceinline__ void gemm_body(
    const float* __restrict__ A, const float* __restrict__ B, float* __restrict__ C,
    int N, int K, int brow, int bcol, float* As, float* Bs)
{
    const int tid  = threadIdx.x;
    const int ty = tid >> 4;          // 0..15
    const int tx = tid & 15;          // 0..15

    const int arow = tid >> 1;
    const int acol = (tid & 1) * 4;
    const int brw  = tid >> 5;
    const int bcl  = (tid & 31) * 4;

    const float* Ap = A + (size_t)(brow + arow) * K + acol;
    const float* Bp = B + (size_t)brw * N + bcol + bcl;

    ull acc[8][4];
#pragma unroll
    for (int i = 0; i < 8; i++)
#pragma unroll
        for (int j = 0; j < 4; j++) acc[i][j] = 0ULL;

    float4 a = *(const float4*)Ap;
    float4 b4 = *(const float4*)Bp;
    As[(acol + 0) * LDA_S + arow] = a.x;
    As[(acol + 1) * LDA_S + arow] = a.y;
    As[(acol + 2) * LDA_S + arow] = a.z;
    As[(acol + 3) * LDA_S + arow] = a.w;
    *(float4*)&Bs[brw * 128 + bcl] = b4;
    __syncthreads();

    int buf = 0;
    for (int k0 = 0; k0 < K; k0 += 8) {
        const bool has_next = (k0 + 8 < K);
        if (has_next) {
            a  = *(const float4*)(Ap + k0 + 8);
            b4 = *(const float4*)(Bp + (size_t)(k0 + 8) * N);
        }
        const float* Asc = As + buf * AS_STRIDE;
        const float* Bsc = Bs + buf * BS_STRIDE;

#pragma unroll
        for (int kk = 0; kk < 8; kk++) {
            float4 a0 = *(const float4*)&Asc[kk * LDA_S + ty * 8];
            float4 a1 = *(const float4*)&Asc[kk * LDA_S + ty * 8 + 4];
            ulonglong2 bA = *(const ulonglong2*)&Bsc[kk * 128 + tx * 4];
            ulonglong2 bB = *(const ulonglong2*)&Bsc[kk * 128 + 64 + tx * 4];
            float av[8] = {a0.x, a0.y, a0.z, a0.w, a1.x, a1.y, a1.z, a1.w};
#pragma unroll
            for (int i = 0; i < 8; i++) {
                ull aa = pack2(av[i], av[i]);
                acc[i][0] = ffma2(aa, bA.x, acc[i][0]);
                acc[i][1] = ffma2(aa, bA.y, acc[i][1]);
                acc[i][2] = ffma2(aa, bB.x, acc[i][2]);
                acc[i][3] = ffma2(aa, bB.y, acc[i][3]);
            }
        }

        if (has_next) {
            float* Asn = As + (buf ^ 1) * AS_STRIDE;
            float* Bsn = Bs + (buf ^ 1) * BS_STRIDE;
            Asn[(acol + 0) * LDA_S + arow] = a.x;
            Asn[(acol + 1) * LDA_S + arow] = a.y;
            Asn[(acol + 2) * LDA_S + arow] = a.z;
            Asn[(acol + 3) * LDA_S + arow] = a.w;
            *(float4*)&Bsn[brw * 128 + bcl] = b4;
        }
        __syncthreads();
        buf ^= 1;
    }

#pragma unroll
    for (int i = 0; i < 8; i++) {
        float* crow = C + (size_t)(brow + ty * 8 + i) * N + bcol;
        float x0, y0, x1, y1;
        unpack2(acc[i][0], x0, y0); unpack2(acc[i][1], x1, y1);
        *(float4*)&crow[tx * 4] = make_float4(x0, y0, x1, y1);
        unpack2(acc[i][2], x0, y0); unpack2(acc[i][3], x1, y1);
        *(float4*)&crow[64 + tx * 4] = make_float4(x0, y0, x1, y1);
    }
}

__global__ __launch_bounds__(256) void qkv_kernel(
    const float* __restrict__ x,
    const float* __restrict__ wq, const float* __restrict__ wk, const float* __restrict__ wv,
    float* __restrict__ Qb, float* __restrict__ Kb, float* __restrict__ Vb)
{
    __shared__ float As[2 * AS_STRIDE];
    __shared__ float Bs[2 * BS_STRIDE];
    const int bx = blockIdx.x;
    const int brow = blockIdx.y * 128;
    if (bx < 8) {
        gemm_body(x, wq, Qb, DMODEL, DMODEL, brow, bx * 128, As, Bs);
    } else if (bx < 10) {
        gemm_body(x, wk, Kb, NKV * HD, DMODEL, brow, (bx - 8) * 128, As, Bs);
    } else {
        gemm_body(x, wv, Vb, NKV * HD, DMODEL, brow, (bx - 10) * 128, As, Bs);
    }
}

__global__ __launch_bounds__(256) void wo_kernel(
    const float* __restrict__ A, const float* __restrict__ B, float* __restrict__ C)
{
    __shared__ float As[2 * AS_STRIDE];
    __shared__ float Bs[2 * BS_STRIDE];
    gemm_body(A, B, C, DMODEL, DMODEL, blockIdx.y * 128, blockIdx.x * 128, As, Bs);
}

// ---------------- RoPE Q (in place) ----------------
__global__ void rope_q_kernel(float* __restrict__ X,
                              const float* __restrict__ cosT,
                              const float* __restrict__ sinT)
{
    int idx = blockIdx.x * blockDim.x + threadIdx.x;
    int d    = idx & 31;
    int rest = idx >> 5;
    int head = rest & (NH - 1);
    int row  = rest >> 4;
    int s    = row & (SEQ - 1);
    float c  = cosT[s * 32 + d];
    float sn = sinT[s * 32 + d];
    float* p = X + (size_t)row * NH * HD + head * HD + d;
    float a = p[0], b = p[32];
    p[0]  = a * c - b * sn;
    p[32] = b * c + a * sn;
}

// ---------------- RoPE K (in place) + transposed copy KT[b][kv][d][s] ----------------
__global__ void rope_k_kernel(float* __restrict__ X,
                              float* __restrict__ KT,
                              const float* __restrict__ cosT,
                              const float* __restrict__ sinT)
{
    int idx = blockIdx.x * blockDim.x + threadIdx.x;
    int d    = idx & 31;
    int rest = idx >> 5;
    int head = rest & (NKV - 1);
    int row  = rest >> 2;
    int s    = row & (SEQ - 1);
    int b    = row >> 11;
    float c  = cosT[s * 32 + d];
    float sn = sinT[s * 32 + d];
    float* p = X + (size_t)row * NKV * HD + head * HD + d;
    float a = p[0], bb = p[32];
    float na = a * c - bb * sn;
    float nb = bb * c + a * sn;
    p[0]  = na;
    p[32] = nb;
    float* kt = KT + ((size_t)(b * NKV + head) * HD) * SEQ;
    kt[(size_t)d * SEQ + s]        = na;
    kt[(size_t)(d + 32) * SEQ + s] = nb;
}

// ---------------- Flash attention v4 (fp32, causal, GQA) ----------------
// 128-query x 64-key tiles, 128 threads = 4 warps. Thread tile 8 rows x 8 cols.
// Rows interleaved: row(i) = w*32 + i*4 + ry.  Cols split: {cx*4..+3} u {32+cx*4..+3}.
#define LDQ 68
#define LDK 68
#define LDV 64
#define LDP 68
#define QROWS 128
#define FLASH_SMEM ((QROWS*LDQ + 64*LDK + 64*LDV + QROWS*LDP) * 4)

__global__ __launch_bounds__(128, 2) void flash_kernel(
    const float* __restrict__ Q,    // [4096,1024] (rope'd)
    const float* __restrict__ KT,   // [b][kv][64][2048]
    const float* __restrict__ V,    // [4096,256]
    float* __restrict__ O)
{
    extern __shared__ float sm[];
    float* Qs = sm;                      // [r][d]  128 x LDQ
    float* Ks = Qs + QROWS * LDQ;        // [d][c]  64 x LDK
    float* Vs = Ks + 64 * LDK;           // [k][d]  64 x LDV
    float* Ps = Vs + 64 * LDV;           // [r][k]  128 x LDP

    const int tid  = threadIdx.x;
    const int w    = tid >> 5;
    const int lane = tid & 31;
    const int ry   = lane >> 3;
    const int cx   = lane & 7;
    const int r0   = w * 32 + ry;        // thread rows: r0 + 4*i, i=0..7
    const int cb0  = cx * 4;             // col group 0
    const int cb1  = 32 + cx * 4;        // col group 1

    const int mt = gridDim.x - 1 - blockIdx.x;   // heavy blocks first
    const int bh = blockIdx.y;
    const int b  = bh >> 4;
    const int h  = bh & 15;
    const int kv = h >> 2;

    const float* Qg  = Q + ((size_t)(b * SEQ + mt * QROWS)) * DMODEL + h * HD;
    const float* KTg = KT + ((size_t)(b * NKV + kv) * HD) * SEQ;
    const float* Vg  = V + ((size_t)(b * SEQ)) * (NKV * HD) + kv * HD;

    // load Q tile [128 x 64], fold in 1/sqrt(HD)
#pragma unroll
    for (int i = 0; i < 16; i++) {
        int idx = tid + i * 128;
        int r = idx >> 4;
        int d4 = (idx & 15) * 4;
        float4 t = *(const float4*)(Qg + (size_t)r * DMODEL + d4);
        t.x *= 0.125f; t.y *= 0.125f; t.z *= 0.125f; t.w *= 0.125f;
        *(float4*)&Qs[r * LDQ + d4] = t;
    }

    ull o2[8][4];
    float m[8], l[8];
#pragma unroll
    for (int i = 0; i < 8; i++) {
        m[i] = -1e30f; l[i] = 0.f;
#pragma unroll
        for (int j = 0; j < 4; j++) o2[i][j] = 0ULL;
    }

    const int ktmax = 2 * mt + 1;
    for (int kt = 0; kt <= ktmax; kt++) {
        __syncthreads();   // prior PV reads of Vs done before overwrite
        // load K^T tile [64 x 64] and V tile [64 x 64]
#pragma unroll
        for (int i = 0; i < 8; i++) {
            int idx = tid + i * 128;
            int r  = idx >> 4;
            int c4 = (idx & 15) * 4;
            float4 t = *(const float4*)(KTg + (size_t)r * SEQ + kt * 64 + c4);
            *(float4*)&Ks[r * LDK + c4] = t;
            float4 vv = *(const float4*)(Vg + (size_t)(kt * 64 + r) * (NKV * HD) + c4);
            *(float4*)&Vs[r * LDV + c4] = vv;
        }
        __syncthreads();

        // last diagonal tile: warps 0,1 (rows 0..63) are fully masked — uniform per warp
        const bool skip = (kt == ktmax) && (w < 2);
        float al[8];

        if (!skip) {
            // S = Q @ K^T
            ull s2[8][4];
#pragma unroll
            for (int i = 0; i < 8; i++)
#pragma unroll
                for (int j = 0; j < 4; j++) s2[i][j] = 0ULL;

            for (int d0 = 0; d0 < 64; d0 += 4) {
                float4 q4[8];
#pragma unroll
                for (int i = 0; i < 8; i++)
                    q4[i] = *(const float4*)&Qs[(r0 + i * 4) * LDQ + d0];
#pragma unroll
                for (int dd = 0; dd < 4; dd++) {
                    const float* kr = &Ks[(d0 + dd) * LDK];
                    ulonglong2 kA = *(const ulonglong2*)(kr + cb0);
                    ulonglong2 kB = *(const ulonglong2*)(kr + cb1);
#pragma unroll
                    for (int i = 0; i < 8; i++) {
                        float qv = (dd == 0) ? q4[i].x : (dd == 1) ? q4[i].y
                                 : (dd == 2) ? q4[i].z : q4[i].w;
                        ull aa = pack2(qv, qv);
                        s2[i][0] = ffma2(aa, kA.x, s2[i][0]);
                        s2[i][1] = ffma2(aa, kA.y, s2[i][1]);
                        s2[i][2] = ffma2(aa, kB.x, s2[i][2]);
                        s2[i][3] = ffma2(aa, kB.y, s2[i][3]);
                    }
                }
            }

            float s[8][8];
#pragma unroll
            for (int i = 0; i < 8; i++)
#pragma unroll
                for (int j = 0; j < 4; j++)
                    unpack2(s2[i][j], s[i][2 * j], s[i][2 * j + 1]);

            if (kt >= 2 * mt) {   // partially masked tiles
#pragma unroll
                for (int i = 0; i < 8; i++) {
                    int rglob = mt * QROWS + r0 + i * 4;
#pragma unroll
                    for (int c = 0; c < 8; c++) {
                        int kglob = kt * 64 + ((c < 4) ? (cb0 + c) : (cb1 + c - 4));
                        if (kglob > rglob) s[i][c] = -1e9f;
                    }
                }
            }

            // online softmax per row (reduce over 8 cx lanes)
#pragma unroll
            for (int i = 0; i < 8; i++) {
                float mx = s[i][0];
#pragma unroll
                for (int c = 1; c < 8; c++) mx = fmaxf(mx, s[i][c]);
                mx = fmaxf(mx, __shfl_xor_sync(0xffffffffu, mx, 1));
                mx = fmaxf(mx, __shfl_xor_sync(0xffffffffu, mx, 2));
                mx = fmaxf(mx, __shfl_xor_sync(0xffffffffu, mx, 4));
                float mnew = fmaxf(m[i], mx);
                float alpha = __expf(m[i] - mnew);
                float sum = 0.f;
#pragma unroll
                for (int c = 0; c < 8; c++) {
                    float p = __expf(s[i][c] - mnew);
                    s[i][c] = p;
                    sum += p;
                }
                sum += __shfl_xor_sync(0xffffffffu, sum, 1);
                sum += __shfl_xor_sync(0xffffffffu, sum, 2);
                sum += __shfl_xor_sync(0xffffffffu, sum, 4);
                l[i] = l[i] * alpha + sum;
                m[i] = mnew;
                al[i] = alpha;
            }

            // write P rows (cols cb0..cb0+3, cb1..cb1+3)
#pragma unroll
            for (int i = 0; i < 8; i++) {
                float* pr = &Ps[(r0 + i * 4) * LDP];
                *(float4*)(pr + cb0) = make_float4(s[i][0], s[i][1], s[i][2], s[i][3]);
                *(float4*)(pr + cb1) = make_float4(s[i][4], s[i][5], s[i][6], s[i][7]);
            }
        }
        __syncwarp();    // P rows are warp-local: warp-level visibility suffices

        if (!skip) {
            // rescale O, accumulate O += P @ V
#pragma unroll
            for (int i = 0; i < 8; i++) {
                ull a2 = pack2(al[i], al[i]);
#pragma unroll
                for (int j = 0; j < 4; j++) o2[i][j] = mul2(o2[i][j], a2);
            }
            for (int k0 = 0; k0 < 64; k0 += 4) {
                float4 p4[8];
#pragma unroll
                for (int i = 0; i < 8; i++)
                    p4[i] = *(const float4*)&Ps[(r0 + i * 4) * LDP + k0];
#pragma unroll
                for (int kk = 0; kk < 4; kk++) {
                    const float* vr = &Vs[(k0 + kk) * LDV];
                    ulonglong2 vA = *(const ulonglong2*)(vr + cb0);
                    ulonglong2 vB = *(const ulonglong2*)(vr + cb1);
#pragma unroll
                    for (int i = 0; i < 8; i++) {
                        float pv = (kk == 0) ? p4[i].x : (kk == 1) ? p4[i].y
                                 : (kk == 2) ? p4[i].z : p4[i].w;
                        ull pa = pack2(pv, pv);
                        o2[i][0] = ffma2(pa, vA.x, o2[i][0]);
                        o2[i][1] = ffma2(pa, vA.y, o2[i][1]);
                        o2[i][2] = ffma2(pa, vB.x, o2[i][2]);
                        o2[i][3] = ffma2(pa, vB.y, o2[i][3]);
                    }
                }
            }
        }
    }

    // epilogue: O /= l, write (cols cb0 and cb1, 16B coalesced per group)
#pragma unroll
    for (int i = 0; i < 8; i++) {
        float inv = 1.0f / l[i];
        size_t row = (size_t)(b * SEQ + mt * QROWS + r0 + i * 4);
        float* op = O + row * DMODEL + h * HD;
        float x0, y0, x1, y1;
        unpack2(o2[i][0], x0, y0); unpack2(o2[i][1], x1, y1);
        *(float4*)&op[cb0] = make_float4(x0 * inv, y0 * inv, x1 * inv, y1 * inv);
        unpack2(o2[i][2], x0, y0); unpack2(o2[i][3], x1, y1);
        *(float4*)&op[cb1] = make_float4(x0 * inv, y0 * inv, x1 * inv, y1 * inv);
    }
}

// ---------------- launch ----------------
extern "C" void kernel_launch(void* const* d_in, const int* in_sizes, int n_in,
                              void* d_out, int out_size)
{
    const float* x    = (const float*)d_in[0];
    const float* cosT = (const float*)d_in[1];
    const float* sinT = (const float*)d_in[2];
    // d_in[3] = mask (causal, reproduced analytically)
    const float* wq   = (const float*)d_in[4];
    const float* wk   = (const float*)d_in[5];
    const float* wv   = (const float*)d_in[6];
    const float* wo   = (const float*)d_in[7];

    float* out  = (float*)d_out;                       // [2,2048,1024]
    float* knew = out + (size_t)ROWS * DMODEL;         // [2,2048,4,64]
    float* vnew = knew + (size_t)ROWS * NKV * HD;      // [2,2048,4,64]

    float *Qbuf = nullptr, *AObuf = nullptr, *KTbuf = nullptr;
    cudaGetSymbolAddress((void**)&Qbuf, g_Q);
    cudaGetSymbolAddress((void**)&AObuf, g_AO);
    cudaGetSymbolAddress((void**)&KTbuf, g_KT);
    cudaFuncSetAttribute(flash_kernel, cudaFuncAttributeMaxDynamicSharedMemorySize, FLASH_SMEM);

    // fused QKV projections (one launch, 384 blocks)
    qkv_kernel<<<dim3(12, ROWS / 128), 256>>>(x, wq, wk, wv, Qbuf, knew, vnew);

    // RoPE: Q in place; K in place + transposed copy
    rope_q_kernel<<<(ROWS * NH * 32) / 256, 256>>>(Qbuf, cosT, sinT);
    rope_k_kernel<<<(ROWS * NKV * 32) / 256, 256>>>(knew, KTbuf, cosT, sinT);

    // attention
    flash_kernel<<<dim3(SEQ / QROWS, BATCH * NH), 128, FLASH_SMEM>>>(Qbuf, KTbuf, vnew, AObuf);

    // output projection
    wo_kernel<<<dim3(DMODEL / 128, ROWS / 128), 256>>>(AObuf, wo, out);
}

// round 5
// speedup vs baseline: 1.6609x; 1.0653x over previous
#include <cuda_runtime.h>
#include <cuda_bf16.h>
#include <cstddef>

using ull = unsigned long long;

// ---------------- packed f32x2 helpers (Blackwell FFMA2 path) ----------------
__device__ __forceinline__ ull pack2(float x, float y) {
    ull r; asm("mov.b64 %0, {%1, %2};" : "=l"(r) : "f"(x), "f"(y)); return r;
}
__device__ __forceinline__ void unpack2(ull v, float& x, float& y) {
    asm("mov.b64 {%0, %1}, %2;" : "=f"(x), "=f"(y) : "l"(v));
}
__device__ __forceinline__ ull ffma2(ull a, ull b, ull c) {
    ull d; asm("fma.rn.f32x2 %0, %1, %2, %3;" : "=l"(d) : "l"(a), "l"(b), "l"(c)); return d;
}
__device__ __forceinline__ ull mul2(ull a, ull b) {
    ull d; asm("mul.rn.f32x2 %0, %1, %2;" : "=l"(d) : "l"(a), "l"(b)); return d;
}

// ---------------- problem constants ----------------
#define BATCH 2
#define SEQ   2048
#define DMODEL 1024
#define NH    16
#define NKV   4
#define HD    64
#define ROWS  (BATCH*SEQ)     // 4096

__device__ float g_Q[ROWS * DMODEL];            // Q after projection (rope fused into flash)
__device__ float g_AO[ROWS * DMODEL];           // attention output before Wo
__device__ float g_KT[BATCH * NKV * HD * SEQ];  // K^T: [b][kv][d][s]

// ---------------- GEMM tile body (R4, unchanged) ----------------
#define LDA_S 132
#define AS_STRIDE (8 * LDA_S)
#define BS_STRIDE (8 * 128)

__device__ __forceinline__ void gemm_body(
    const float* __restrict__ A, const float* __restrict__ B, float* __restrict__ C,
    int N, int K, int brow, int bcol, float* As, float* Bs)
{
    const int tid  = threadIdx.x;
    const int ty = tid >> 4;
    const int tx = tid & 15;

    const int arow = tid >> 1;
    const int acol = (tid & 1) * 4;
    const int brw  = tid >> 5;
    const int bcl  = (tid & 31) * 4;

    const float* Ap = A + (size_t)(brow + arow) * K + acol;
    const float* Bp = B + (size_t)brw * N + bcol + bcl;

    ull acc[8][4];
#pragma unroll
    for (int i = 0; i < 8; i++)
#pragma unroll
        for (int j = 0; j < 4; j++) acc[i][j] = 0ULL;

    float4 a = *(const float4*)Ap;
    float4 b4 = *(const float4*)Bp;
    As[(acol + 0) * LDA_S + arow] = a.x;
    As[(acol + 1) * LDA_S + arow] = a.y;
    As[(acol + 2) * LDA_S + arow] = a.z;
    As[(acol + 3) * LDA_S + arow] = a.w;
    *(float4*)&Bs[brw * 128 + bcl] = b4;
    __syncthreads();

    int buf = 0;
    for (int k0 = 0; k0 < K; k0 += 8) {
        const bool has_next = (k0 + 8 < K);
        if (has_next) {
            a  = *(const float4*)(Ap + k0 + 8);
            b4 = *(const float4*)(Bp + (size_t)(k0 + 8) * N);
        }
        const float* Asc = As + buf * AS_STRIDE;
        const float* Bsc = Bs + buf * BS_STRIDE;

#pragma unroll
        for (int kk = 0; kk < 8; kk++) {
            float4 a0 = *(const float4*)&Asc[kk * LDA_S + ty * 8];
            float4 a1 = *(const float4*)&Asc[kk * LDA_S + ty * 8 + 4];
            ulonglong2 bA = *(const ulonglong2*)&Bsc[kk * 128 + tx * 4];
            ulonglong2 bB = *(const ulonglong2*)&Bsc[kk * 128 + 64 + tx * 4];
            float av[8] = {a0.x, a0.y, a0.z, a0.w, a1.x, a1.y, a1.z, a1.w};
#pragma unroll
            for (int i = 0; i < 8; i++) {
                ull aa = pack2(av[i], av[i]);
                acc[i][0] = ffma2(aa, bA.x, acc[i][0]);
                acc[i][1] = ffma2(aa, bA.y, acc[i][1]);
                acc[i][2] = ffma2(aa, bB.x, acc[i][2]);
                acc[i][3] = ffma2(aa, bB.y, acc[i][3]);
            }
        }

        if (has_next) {
            float* Asn = As + (buf ^ 1) * AS_STRIDE;
            float* Bsn = Bs + (buf ^ 1) * BS_STRIDE;
            Asn[(acol + 0) * LDA_S + arow] = a.x;
            Asn[(acol + 1) * LDA_S + arow] = a.y;
            Asn[(acol + 2) * LDA_S + arow] = a.z;
            Asn[(acol + 3) * LDA_S + arow] = a.w;
            *(float4*)&Bsn[brw * 128 + bcl] = b4;
        }
        __syncthreads();
        buf ^= 1;
    }

#pragma unroll
    for (int i = 0; i < 8; i++) {
        float* crow = C + (size_t)(brow + ty * 8 + i) * N + bcol;
        float x0, y0, x1, y1;
        unpack2(acc[i][0], x0, y0); unpack2(acc[i][1], x1, y1);
        *(float4*)&crow[tx * 4] = make_float4(x0, y0, x1, y1);
        unpack2(acc[i][2], x0, y0); unpack2(acc[i][3], x1, y1);
        *(float4*)&crow[64 + tx * 4] = make_float4(x0, y0, x1, y1);
    }
}

__global__ __launch_bounds__(256) void qkv_kernel(
    const float* __restrict__ x,
    const float* __restrict__ wq, const float* __restrict__ wk, const float* __restrict__ wv,
    float* __restrict__ Qb, float* __restrict__ Kb, float* __restrict__ Vb)
{
    __shared__ float As[2 * AS_STRIDE];
    __shared__ float Bs[2 * BS_STRIDE];
    const int bx = blockIdx.x;
    const int brow = blockIdx.y * 128;
    if (bx < 8) {
        gemm_body(x, wq, Qb, DMODEL, DMODEL, brow, bx * 128, As, Bs);
    } else if (bx < 10) {
        gemm_body(x, wk, Kb, NKV * HD, DMODEL, brow, (bx - 8) * 128, As, Bs);
    } else {
        gemm_body(x, wv, Vb, NKV * HD, DMODEL, brow, (bx - 10) * 128, As, Bs);
    }
}

__global__ __launch_bounds__(256) void wo_kernel(
    const float* __restrict__ A, const float* __restrict__ B, float* __restrict__ C)
{
    __shared__ float As[2 * AS_STRIDE];
    __shared__ float Bs[2 * BS_STRIDE];
    gemm_body(A, B, C, DMODEL, DMODEL, blockIdx.y * 128, blockIdx.x * 128, As, Bs);
}

// ---------------- RoPE K (in place) + transposed copy KT[b][kv][d][s] ----------------
__global__ void rope_k_kernel(float* __restrict__ X,
                              float* __restrict__ KT,
                              const float* __restrict__ cosT,
                              const float* __restrict__ sinT)
{
    int idx = blockIdx.x * blockDim.x + threadIdx.x;
    int d    = idx & 31;
    int rest = idx >> 5;
    int head = rest & (NKV - 1);
    int row  = rest >> 2;
    int s    = row & (SEQ - 1);
    int b    = row >> 11;
    float c  = cosT[s * 32 + d];
    float sn = sinT[s * 32 + d];
    float* p = X + (size_t)row * NKV * HD + head * HD + d;
    float a = p[0], bb = p[32];
    float na = a * c - bb * sn;
    float nb = bb * c + a * sn;
    p[0]  = na;
    p[32] = nb;
    float* kt = KT + ((size_t)(b * NKV + head) * HD) * SEQ;
    kt[(size_t)d * SEQ + s]        = na;
    kt[(size_t)(d + 32) * SEQ + s] = nb;
}

// ---------------- Flash attention v5 (fp32, causal, GQA) ----------------
// 64-query x 64-key tiles, 128 threads = 4 warps, 3 CTAs/SM.
// Thread tile 4 rows x 8 cols. Rows: r0 = w*16 + ry, +4i. Cols: {cx*4} u {32+cx*4}.
// RoPE on Q fused into the Q smem load.
#define LDQ 68
#define LDK 68
#define LDV 64
#define LDP 68
#define QR 64
#define FLASH_SMEM ((QR*LDQ + 64*LDK + 64*LDV + QR*LDP) * 4)

__global__ __launch_bounds__(128, 3) void flash_kernel(
    const float* __restrict__ Q,    // [4096,1024] (projection output, no rope yet)
    const float* __restrict__ KT,   // [b][kv][64][2048] (rope'd)
    const float* __restrict__ V,    // [4096,256]
    const float* __restrict__ cosT, // [2048,32]
    const float* __restrict__ sinT, // [2048,32]
    float* __restrict__ O)
{
    extern __shared__ float sm[];
    float* Qs = sm;                      // [r][d]  64 x LDQ
    float* Ks = Qs + QR * LDQ;           // [d][c]  64 x LDK
    float* Vs = Ks + 64 * LDK;           // [k][d]  64 x LDV
    float* Ps = Vs + 64 * LDV;           // [r][k]  64 x LDP

    const int tid  = threadIdx.x;
    const int w    = tid >> 5;
    const int lane = tid & 31;
    const int ry   = lane >> 3;
    const int cx   = lane & 7;
    const int r0   = w * 16 + ry;        // thread rows: r0 + 4*i, i=0..3
    const int cb0  = cx * 4;
    const int cb1  = 32 + cx * 4;

    const int mt = gridDim.x - 1 - blockIdx.x;   // heavy blocks first
    const int bh = blockIdx.y;
    const int b  = bh >> 4;
    const int h  = bh & 15;
    const int kv = h >> 2;

    const float* Qg  = Q + ((size_t)(b * SEQ + mt * QR)) * DMODEL + h * HD;
    const float* KTg = KT + ((size_t)(b * NKV + kv) * HD) * SEQ;
    const float* Vg  = V + ((size_t)(b * SEQ)) * (NKV * HD) + kv * HD;

    // load Q tile [64 x 64] with fused RoPE + 1/sqrt(HD) scale
#pragma unroll
    for (int i = 0; i < 4; i++) {
        int idx = tid + i * 128;       // 0..511 over 64 rows x 8 chunks
        int r = idx >> 3;
        int d = (idx & 7) * 4;         // 0..28
        int s = mt * QR + r;
        float4 qa = *(const float4*)(Qg + (size_t)r * DMODEL + d);
        float4 qb = *(const float4*)(Qg + (size_t)r * DMODEL + d + 32);
        float4 c  = *(const float4*)(cosT + s * 32 + d);
        float4 sn = *(const float4*)(sinT + s * 32 + d);
        float4 lo, hi;
        lo.x = (qa.x * c.x - qb.x * sn.x) * 0.125f;
        lo.y = (qa.y * c.y - qb.y * sn.y) * 0.125f;
        lo.z = (qa.z * c.z - qb.z * sn.z) * 0.125f;
        lo.w = (qa.w * c.w - qb.w * sn.w) * 0.125f;
        hi.x = (qb.x * c.x + qa.x * sn.x) * 0.125f;
        hi.y = (qb.y * c.y + qa.y * sn.y) * 0.125f;
        hi.z = (qb.z * c.z + qa.z * sn.z) * 0.125f;
        hi.w = (qb.w * c.w + qa.w * sn.w) * 0.125f;
        *(float4*)&Qs[r * LDQ + d]      = lo;
        *(float4*)&Qs[r * LDQ + d + 32] = hi;
    }

    ull o2[4][4];
    float m[4], l[4];
#pragma unroll
    for (int i = 0; i < 4; i++) {
        m[i] = -1e30f; l[i] = 0.f;
#pragma unroll
        for (int j = 0; j < 4; j++) o2[i][j] = 0ULL;
    }

    for (int kt = 0; kt <= mt; kt++) {
        __syncthreads();   // prior tile reads done before overwrite
        // load K^T tile [64 x 64] and V tile [64 x 64]
#pragma unroll
        for (int i = 0; i < 8; i++) {
            int idx = tid + i * 128;
            int r  = idx >> 4;
            int c4 = (idx & 15) * 4;
            float4 t = *(const float4*)(KTg + (size_t)r * SEQ + kt * 64 + c4);
            *(float4*)&Ks[r * LDK + c4] = t;
            float4 vv = *(const float4*)(Vg + (size_t)(kt * 64 + r) * (NKV * HD) + c4);
            *(float4*)&Vs[r * LDV + c4] = vv;
        }
        __syncthreads();

        // S = Q @ K^T
        ull s2[4][4];
#pragma unroll
        for (int i = 0; i < 4; i++)
#pragma unroll
            for (int j = 0; j < 4; j++) s2[i][j] = 0ULL;

        for (int d0 = 0; d0 < 64; d0 += 4) {
            float4 q4[4];
#pragma unroll
            for (int i = 0; i < 4; i++)
                q4[i] = *(const float4*)&Qs[(r0 + i * 4) * LDQ + d0];
#pragma unroll
            for (int dd = 0; dd < 4; dd++) {
                const float* kr = &Ks[(d0 + dd) * LDK];
                ulonglong2 kA = *(const ulonglong2*)(kr + cb0);
                ulonglong2 kB = *(const ulonglong2*)(kr + cb1);
#pragma unroll
                for (int i = 0; i < 4; i++) {
                    float qv = (dd == 0) ? q4[i].x : (dd == 1) ? q4[i].y
                             : (dd == 2) ? q4[i].z : q4[i].w;
                    ull aa = pack2(qv, qv);
                    s2[i][0] = ffma2(aa, kA.x, s2[i][0]);
                    s2[i][1] = ffma2(aa, kA.y, s2[i][1]);
                    s2[i][2] = ffma2(aa, kB.x, s2[i][2]);
                    s2[i][3] = ffma2(aa, kB.y, s2[i][3]);
                }
            }
        }

        float s[4][8];
#pragma unroll
        for (int i = 0; i < 4; i++)
#pragma unroll
            for (int j = 0; j < 4; j++)
                unpack2(s2[i][j], s[i][2 * j], s[i][2 * j + 1]);

        if (kt == mt) {   // diagonal tile mask
#pragma unroll
            for (int i = 0; i < 4; i++) {
                int rloc = r0 + i * 4;
#pragma unroll
                for (int c = 0; c < 8; c++) {
                    int kloc = (c < 4) ? (cb0 + c) : (cb1 + c - 4);
                    if (kloc > rloc) s[i][c] = -1e9f;
                }
            }
        }

        // online softmax per row (reduce over 8 cx lanes)
        float al[4];
#pragma unroll
        for (int i = 0; i < 4; i++) {
            float mx = s[i][0];
#pragma unroll
            for (int c = 1; c < 8; c++) mx = fmaxf(mx, s[i][c]);
            mx = fmaxf(mx, __shfl_xor_sync(0xffffffffu, mx, 1));
            mx = fmaxf(mx, __shfl_xor_sync(0xffffffffu, mx, 2));
            mx = fmaxf(mx, __shfl_xor_sync(0xffffffffu, mx, 4));
            float mnew = fmaxf(m[i], mx);
            float alpha = __expf(m[i] - mnew);
            float sum = 0.f;
#pragma unroll
            for (int c = 0; c < 8; c++) {
                float p = __expf(s[i][c] - mnew);
                s[i][c] = p;
                sum += p;
            }
            sum += __shfl_xor_sync(0xffffffffu, sum, 1);
            sum += __shfl_xor_sync(0xffffffffu, sum, 2);
            sum += __shfl_xor_sync(0xffffffffu, sum, 4);
            l[i] = l[i] * alpha + sum;
            m[i] = mnew;
            al[i] = alpha;
        }

        // write P rows (warp-local)
#pragma unroll
        for (int i = 0; i < 4; i++) {
            float* pr = &Ps[(r0 + i * 4) * LDP];
            *(float4*)(pr + cb0) = make_float4(s[i][0], s[i][1], s[i][2], s[i][3]);
            *(float4*)(pr + cb1) = make_float4(s[i][4], s[i][5], s[i][6], s[i][7]);
        }
        __syncwarp();

        // rescale O, accumulate O += P @ V
#pragma unroll
        for (int i = 0; i < 4; i++) {
            ull a2 = pack2(al[i], al[i]);
#pragma unroll
            for (int j = 0; j < 4; j++) o2[i][j] = mul2(o2[i][j], a2);
        }
        for (int k0 = 0; k0 < 64; k0 += 4) {
            float4 p4[4];
#pragma unroll
            for (int i = 0; i < 4; i++)
                p4[i] = *(const float4*)&Ps[(r0 + i * 4) * LDP + k0];
#pragma unroll
            for (int kk = 0; kk < 4; kk++) {
                const float* vr = &Vs[(k0 + kk) * LDV];
                ulonglong2 vA = *(const ulonglong2*)(vr + cb0);
                ulonglong2 vB = *(const ulonglong2*)(vr + cb1);
#pragma unroll
                for (int i = 0; i < 4; i++) {
                    float pv = (kk == 0) ? p4[i].x : (kk == 1) ? p4[i].y
                             : (kk == 2) ? p4[i].z : p4[i].w;
                    ull pa = pack2(pv, pv);
                    o2[i][0] = ffma2(pa, vA.x, o2[i][0]);
                    o2[i][1] = ffma2(pa, vA.y, o2[i][1]);
                    o2[i][2] = ffma2(pa, vB.x, o2[i][2]);
                    o2[i][3] = ffma2(pa, vB.y, o2[i][3]);
                }
            }
        }
    }

    // epilogue: O /= l
#pragma unroll
    for (int i = 0; i < 4; i++) {
        float inv = 1.0f / l[i];
        size_t row = (size_t)(b * SEQ + mt * QR + r0 + i * 4);
        float* op = O + row * DMODEL + h * HD;
        float x0, y0, x1, y1;
        unpack2(o2[i][0], x0, y0); unpack2(o2[i][1], x1, y1);
        *(float4*)&op[cb0] = make_float4(x0 * inv, y0 * inv, x1 * inv, y1 * inv);
        unpack2(o2[i][2], x0, y0); unpack2(o2[i][3], x1, y1);
        *(float4*)&op[cb1] = make_float4(x0 * inv, y0 * inv, x1 * inv, y1 * inv);
    }
}

// ---------------- launch ----------------
extern "C" void kernel_launch(void* const* d_in, const int* in_sizes, int n_in,
                              void* d_out, int out_size)
{
    const float* x    = (const float*)d_in[0];
    const float* cosT = (const float*)d_in[1];
    const float* sinT = (const float*)d_in[2];
    // d_in[3] = mask (causal, reproduced analytically)
    const float* wq   = (const float*)d_in[4];
    const float* wk   = (const float*)d_in[5];
    const float* wv   = (const float*)d_in[6];
    const float* wo   = (const float*)d_in[7];

    float* out  = (float*)d_out;                       // [2,2048,1024]
    float* knew = out + (size_t)ROWS * DMODEL;         // [2,2048,4,64]
    float* vnew = knew + (size_t)ROWS * NKV * HD;      // [2,2048,4,64]

    float *Qbuf = nullptr, *AObuf = nullptr, *KTbuf = nullptr;
    cudaGetSymbolAddress((void**)&Qbuf, g_Q);
    cudaGetSymbolAddress((void**)&AObuf, g_AO);
    cudaGetSymbolAddress((void**)&KTbuf, g_KT);
    cudaFuncSetAttribute(flash_kernel, cudaFuncAttributeMaxDynamicSharedMemorySize, FLASH_SMEM);

    // fused QKV projections
    qkv_kernel<<<dim3(12, ROWS / 128), 256>>>(x, wq, wk, wv, Qbuf, knew, vnew);

    // RoPE K (in place) + K^T scratch; RoPE Q fused into flash
    rope_k_kernel<<<(ROWS * NKV * 32) / 256, 256>>>(knew, KTbuf, cosT, sinT);

    // attention
    flash_kernel<<<dim3(SEQ / QR, BATCH * NH), 128, FLASH_SMEM>>>(
        Qbuf, KTbuf, vnew, cosT, sinT, AObuf);

    // output projection
    wo_kernel<<<dim3(DMODEL / 128, ROWS / 128), 256>>>(AObuf, wo, out);
}

// round 6
// speedup vs baseline: 2.1022x; 1.2657x over previous
#include <cuda_runtime.h>
#include <cuda_bf16.h>
#include <cstddef>
#include <cstdint>

using ull = unsigned long long;

// ---------------- packed f32x2 helpers (flash path) ----------------
__device__ __forceinline__ ull pack2(float x, float y) {
    ull r; asm("mov.b64 %0, {%1, %2};" : "=l"(r) : "f"(x), "f"(y)); return r;
}
__device__ __forceinline__ void unpack2(ull v, float& x, float& y) {
    asm("mov.b64 {%0, %1}, %2;" : "=f"(x), "=f"(y) : "l"(v));
}
__device__ __forceinline__ ull ffma2(ull a, ull b, ull c) {
    ull d; asm("fma.rn.f32x2 %0, %1, %2, %3;" : "=l"(d) : "l"(a), "l"(b), "l"(c)); return d;
}
__device__ __forceinline__ ull mul2(ull a, ull b) {
    ull d; asm("mul.rn.f32x2 %0, %1, %2;" : "=l"(d) : "l"(a), "l"(b)); return d;
}

// ---------------- tf32 helpers ----------------
__device__ __forceinline__ uint32_t tf32_of(float f) {
    uint32_t u; asm("cvt.rna.tf32.f32 %0, %1;" : "=r"(u) : "f"(f)); return u;
}
__device__ __forceinline__ void mma_tf32(float c[4],
    uint32_t a0, uint32_t a1, uint32_t a2, uint32_t a3,
    uint32_t b0, uint32_t b1)
{
    asm volatile("mma.sync.aligned.m16n8k8.row.col.f32.tf32.tf32.f32 "
        "{%0,%1,%2,%3}, {%4,%5,%6,%7}, {%8,%9}, {%0,%1,%2,%3};"
        : "+f"(c[0]), "+f"(c[1]), "+f"(c[2]), "+f"(c[3])
        : "r"(a0), "r"(a1), "r"(a2), "r"(a3), "r"(b0), "r"(b1));
}

// ---------------- problem constants ----------------
#define BATCH 2
#define SEQ   2048
#define DMODEL 1024
#define NH    16
#define NKV   4
#define HD    64
#define ROWS  (BATCH*SEQ)     // 4096

__device__ float g_Q[ROWS * DMODEL];            // Q after projection (rope fused into flash)
__device__ float g_AO[ROWS * DMODEL];           // attention output before Wo
__device__ float g_KT[BATCH * NKV * HD * SEQ];  // K^T: [b][kv][d][s]

// ---------------- TF32 GEMM: C[M,N] = A[M,K] @ B[K,N] ----------------
// BM=BN=128, BK=16, 256 threads = 8 warps (2m x 4n), warp tile 64x32.
// As [m=128][k=16] stride 20 (fragment loads hit all 32 banks).
// Bs [k=16][n=128] stride 136 (likewise conflict-free).
#define BKT   16
#define LDAT  20
#define LDBT  136
#define AS_SZ (128 * LDAT)
#define BS_SZ (BKT * LDBT)

__device__ __forceinline__ void gemm_body_tf32(
    const float* __restrict__ A, const float* __restrict__ B, float* __restrict__ C,
    int N, int K, int brow, int bcol, uint32_t* As, uint32_t* Bs)
{
    const int tid  = threadIdx.x;
    const int w    = tid >> 5;
    const int lane = tid & 31;
    const int wm   = (w >> 2) * 64;     // warp m offset (0,64)
    const int wn   = (w & 3) * 32;      // warp n offset (0..96)
    const int qr   = lane >> 2;         // 0..7
    const int qc   = lane & 3;          // 0..3

    // producer mapping
    const int ar = tid >> 1;            // 0..127 (A row)
    const int ak = (tid & 1) * 8;       // 0 or 8
    const int bk = tid >> 4;            // 0..15  (B k-row)
    const int bc = (tid & 15) * 8;      // 0..120

    const float* Ap = A + (size_t)(brow + ar) * K + ak;
    const float* Bp = B + (size_t)bk * N + bcol + bc;

    float acc[4][4][4];
#pragma unroll
    for (int mt = 0; mt < 4; mt++)
#pragma unroll
        for (int nt = 0; nt < 4; nt++)
#pragma unroll
            for (int i = 0; i < 4; i++) acc[mt][nt][i] = 0.f;

    float4 ra0, ra1, rb0, rb1;
    // prologue: load k0=0
    ra0 = *(const float4*)(Ap);
    ra1 = *(const float4*)(Ap + 4);
    rb0 = *(const float4*)(Bp);
    rb1 = *(const float4*)(Bp + 4);
    {
        uint32_t* Asr = As + ar * LDAT + ak;
        uint4 av0 = make_uint4(tf32_of(ra0.x), tf32_of(ra0.y), tf32_of(ra0.z), tf32_of(ra0.w));
        uint4 av1 = make_uint4(tf32_of(ra1.x), tf32_of(ra1.y), tf32_of(ra1.z), tf32_of(ra1.w));
        *(uint4*)Asr = av0; *(uint4*)(Asr + 4) = av1;
        uint32_t* Bsr = Bs + bk * LDBT + bc;
        uint4 bv0 = make_uint4(tf32_of(rb0.x), tf32_of(rb0.y), tf32_of(rb0.z), tf32_of(rb0.w));
        uint4 bv1 = make_uint4(tf32_of(rb1.x), tf32_of(rb1.y), tf32_of(rb1.z), tf32_of(rb1.w));
        *(uint4*)Bsr = bv0; *(uint4*)(Bsr + 4) = bv1;
    }
    __syncthreads();

    int buf = 0;
    for (int k0 = 0; k0 < K; k0 += BKT) {
        const bool has_next = (k0 + BKT < K);
        if (has_next) {
            ra0 = *(const float4*)(Ap + k0 + BKT);
            ra1 = *(const float4*)(Ap + k0 + BKT + 4);
            rb0 = *(const float4*)(Bp + (size_t)(k0 + BKT) * N);
            rb1 = *(const float4*)(Bp + (size_t)(k0 + BKT) * N + 4);
        }
        const uint32_t* Asb = As + buf * AS_SZ;
        const uint32_t* Bsb = Bs + buf * BS_SZ;

#pragma unroll
        for (int kk = 0; kk < BKT; kk += 8) {
            uint32_t af[4][4];
#pragma unroll
            for (int mt = 0; mt < 4; mt++) {
                const uint32_t* ap = Asb + (wm + mt * 16 + qr) * LDAT + kk + qc;
                af[mt][0] = ap[0];
                af[mt][1] = ap[8 * LDAT];
                af[mt][2] = ap[4];
                af[mt][3] = ap[8 * LDAT + 4];
            }
            uint32_t bf[4][2];
#pragma unroll
            for (int nt = 0; nt < 4; nt++) {
                const uint32_t* bp = Bsb + (kk + qc) * LDBT + wn + nt * 8 + qr;
                bf[nt][0] = bp[0];
                bf[nt][1] = bp[4 * LDBT];
            }
#pragma unroll
            for (int mt = 0; mt < 4; mt++)
#pragma unroll
                for (int nt = 0; nt < 4; nt++)
                    mma_tf32(acc[mt][nt], af[mt][0], af[mt][1], af[mt][2], af[mt][3],
                             bf[nt][0], bf[nt][1]);
        }

        if (has_next) {
            uint32_t* Asr = As + (buf ^ 1) * AS_SZ + ar * LDAT + ak;
            uint4 av0 = make_uint4(tf32_of(ra0.x), tf32_of(ra0.y), tf32_of(ra0.z), tf32_of(ra0.w));
            uint4 av1 = make_uint4(tf32_of(ra1.x), tf32_of(ra1.y), tf32_of(ra1.z), tf32_of(ra1.w));
            *(uint4*)Asr = av0; *(uint4*)(Asr + 4) = av1;
            uint32_t* Bsr = Bs + (buf ^ 1) * BS_SZ + bk * LDBT + bc;
            uint4 bv0 = make_uint4(tf32_of(rb0.x), tf32_of(rb0.y), tf32_of(rb0.z), tf32_of(rb0.w));
            uint4 bv1 = make_uint4(tf32_of(rb1.x), tf32_of(rb1.y), tf32_of(rb1.z), tf32_of(rb1.w));
            *(uint4*)Bsr = bv0; *(uint4*)(Bsr + 4) = bv1;
        }
        __syncthreads();
        buf ^= 1;
    }

    // epilogue: c0,c1 at (qr, 2qc..+1); c2,c3 at (qr+8, 2qc..+1)
#pragma unroll
    for (int mt = 0; mt < 4; mt++) {
#pragma unroll
        for (int nt = 0; nt < 4; nt++) {
            float* crow = C + (size_t)(brow + wm + mt * 16 + qr) * N + bcol + wn + nt * 8 + 2 * qc;
            *(float2*)crow = make_float2(acc[mt][nt][0], acc[mt][nt][1]);
            *(float2*)(crow + (size_t)8 * N) = make_float2(acc[mt][nt][2], acc[mt][nt][3]);
        }
    }
}

__global__ __launch_bounds__(256) void qkv_kernel(
    const float* __restrict__ x,
    const float* __restrict__ wq, const float* __restrict__ wk, const float* __restrict__ wv,
    float* __restrict__ Qb, float* __restrict__ Kb, float* __restrict__ Vb)
{
    __shared__ uint32_t As[2 * AS_SZ];
    __shared__ uint32_t Bs[2 * BS_SZ];
    const int bx = blockIdx.x;
    const int brow = blockIdx.y * 128;
    if (bx < 8) {
        gemm_body_tf32(x, wq, Qb, DMODEL, DMODEL, brow, bx * 128, As, Bs);
    } else if (bx < 10) {
        gemm_body_tf32(x, wk, Kb, NKV * HD, DMODEL, brow, (bx - 8) * 128, As, Bs);
    } else {
        gemm_body_tf32(x, wv, Vb, NKV * HD, DMODEL, brow, (bx - 10) * 128, As, Bs);
    }
}

__global__ __launch_bounds__(256) void wo_kernel(
    const float* __restrict__ A, const float* __restrict__ B, float* __restrict__ C)
{
    __shared__ uint32_t As[2 * AS_SZ];
    __shared__ uint32_t Bs[2 * BS_SZ];
    gemm_body_tf32(A, B, C, DMODEL, DMODEL, blockIdx.y * 128, blockIdx.x * 128, As, Bs);
}

// ---------------- RoPE K (in place) + transposed copy KT[b][kv][d][s] ----------------
__global__ void rope_k_kernel(float* __restrict__ X,
                              float* __restrict__ KT,
                              const float* __restrict__ cosT,
                              const float* __restrict__ sinT)
{
    int idx = blockIdx.x * blockDim.x + threadIdx.x;
    int d    = idx & 31;
    int rest = idx >> 5;
    int head = rest & (NKV - 1);
    int row  = rest >> 2;
    int s    = row & (SEQ - 1);
    int b    = row >> 11;
    float c  = cosT[s * 32 + d];
    float sn = sinT[s * 32 + d];
    float* p = X + (size_t)row * NKV * HD + head * HD + d;
    float a = p[0], bb = p[32];
    float na = a * c - bb * sn;
    float nb = bb * c + a * sn;
    p[0]  = na;
    p[32] = nb;
    float* kt = KT + ((size_t)(b * NKV + head) * HD) * SEQ;
    kt[(size_t)d * SEQ + s]        = na;
    kt[(size_t)(d + 32) * SEQ + s] = nb;
}

// ---------------- Flash attention v5 (fp32, causal, GQA) — unchanged ----------------
#define LDQ 68
#define LDK 68
#define LDV 64
#define LDP 68
#define QR 64
#define FLASH_SMEM ((QR*LDQ + 64*LDK + 64*LDV + QR*LDP) * 4)

__global__ __launch_bounds__(128, 3) void flash_kernel(
    const float* __restrict__ Q,
    const float* __restrict__ KT,
    const float* __restrict__ V,
    const float* __restrict__ cosT,
    const float* __restrict__ sinT,
    float* __restrict__ O)
{
    extern __shared__ float sm[];
    float* Qs = sm;
    float* Ks = Qs + QR * LDQ;
    float* Vs = Ks + 64 * LDK;
    float* Ps = Vs + 64 * LDV;

    const int tid  = threadIdx.x;
    const int w    = tid >> 5;
    const int lane = tid & 31;
    const int ry   = lane >> 3;
    const int cx   = lane & 7;
    const int r0   = w * 16 + ry;
    const int cb0  = cx * 4;
    const int cb1  = 32 + cx * 4;

    const int mt = gridDim.x - 1 - blockIdx.x;
    const int bh = blockIdx.y;
    const int b  = bh >> 4;
    const int h  = bh & 15;
    const int kv = h >> 2;

    const float* Qg  = Q + ((size_t)(b * SEQ + mt * QR)) * DMODEL + h * HD;
    const float* KTg = KT + ((size_t)(b * NKV + kv) * HD) * SEQ;
    const float* Vg  = V + ((size_t)(b * SEQ)) * (NKV * HD) + kv * HD;

#pragma unroll
    for (int i = 0; i < 4; i++) {
        int idx = tid + i * 128;
        int r = idx >> 3;
        int d = (idx & 7) * 4;
        int s = mt * QR + r;
        float4 qa = *(const float4*)(Qg + (size_t)r * DMODEL + d);
        float4 qb = *(const float4*)(Qg + (size_t)r * DMODEL + d + 32);
        float4 c  = *(const float4*)(cosT + s * 32 + d);
        float4 sn = *(const float4*)(sinT + s * 32 + d);
        float4 lo, hi;
        lo.x = (qa.x * c.x - qb.x * sn.x) * 0.125f;
        lo.y = (qa.y * c.y - qb.y * sn.y) * 0.125f;
        lo.z = (qa.z * c.z - qb.z * sn.z) * 0.125f;
        lo.w = (qa.w * c.w - qb.w * sn.w) * 0.125f;
        hi.x = (qb.x * c.x + qa.x * sn.x) * 0.125f;
        hi.y = (qb.y * c.y + qa.y * sn.y) * 0.125f;
        hi.z = (qb.z * c.z + qa.z * sn.z) * 0.125f;
        hi.w = (qb.w * c.w + qa.w * sn.w) * 0.125f;
        *(float4*)&Qs[r * LDQ + d]      = lo;
        *(float4*)&Qs[r * LDQ + d + 32] = hi;
    }

    ull o2[4][4];
    float m[4], l[4];
#pragma unroll
    for (int i = 0; i < 4; i++) {
        m[i] = -1e30f; l[i] = 0.f;
#pragma unroll
        for (int j = 0; j < 4; j++) o2[i][j] = 0ULL;
    }

    for (int kt = 0; kt <= mt; kt++) {
        __syncthreads();
#pragma unroll
        for (int i = 0; i < 8; i++) {
            int idx = tid + i * 128;
            int r  = idx >> 4;
            int c4 = (idx & 15) * 4;
            float4 t = *(const float4*)(KTg + (size_t)r * SEQ + kt * 64 + c4);
            *(float4*)&Ks[r * LDK + c4] = t;
            float4 vv = *(const float4*)(Vg + (size_t)(kt * 64 + r) * (NKV * HD) + c4);
            *(float4*)&Vs[r * LDV + c4] = vv;
        }
        __syncthreads();

        ull s2[4][4];
#pragma unroll
        for (int i = 0; i < 4; i++)
#pragma unroll
            for (int j = 0; j < 4; j++) s2[i][j] = 0ULL;

        for (int d0 = 0; d0 < 64; d0 += 4) {
            float4 q4[4];
#pragma unroll
            for (int i = 0; i < 4; i++)
                q4[i] = *(const float4*)&Qs[(r0 + i * 4) * LDQ + d0];
#pragma unroll
            for (int dd = 0; dd < 4; dd++) {
                const float* kr = &Ks[(d0 + dd) * LDK];
                ulonglong2 kA = *(const ulonglong2*)(kr + cb0);
                ulonglong2 kB = *(const ulonglong2*)(kr + cb1);
#pragma unroll
                for (int i = 0; i < 4; i++) {
                    float qv = (dd == 0) ? q4[i].x : (dd == 1) ? q4[i].y
                             : (dd == 2) ? q4[i].z : q4[i].w;
                    ull aa = pack2(qv, qv);
                    s2[i][0] = ffma2(aa, kA.x, s2[i][0]);
                    s2[i][1] = ffma2(aa, kA.y, s2[i][1]);
                    s2[i][2] = ffma2(aa, kB.x, s2[i][2]);
                    s2[i][3] = ffma2(aa, kB.y, s2[i][3]);
                }
            }
        }

        float s[4][8];
#pragma unroll
        for (int i = 0; i < 4; i++)
#pragma unroll
            for (int j = 0; j < 4; j++)
                unpack2(s2[i][j], s[i][2 * j], s[i][2 * j + 1]);

        if (kt == mt) {
#pragma unroll
            for (int i = 0; i < 4; i++) {
                int rloc = r0 + i * 4;
#pragma unroll
                for (int c = 0; c < 8; c++) {
                    int kloc = (c < 4) ? (cb0 + c) : (cb1 + c - 4);
                    if (kloc > rloc) s[i][c] = -1e9f;
                }
            }
        }

        float al[4];
#pragma unroll
        for (int i = 0; i < 4; i++) {
            float mx = s[i][0];
#pragma unroll
            for (int c = 1; c < 8; c++) mx = fmaxf(mx, s[i][c]);
            mx = fmaxf(mx, __shfl_xor_sync(0xffffffffu, mx, 1));
            mx = fmaxf(mx, __shfl_xor_sync(0xffffffffu, mx, 2));
            mx = fmaxf(mx, __shfl_xor_sync(0xffffffffu, mx, 4));
            float mnew = fmaxf(m[i], mx);
            float alpha = __expf(m[i] - mnew);
            float sum = 0.f;
#pragma unroll
            for (int c = 0; c < 8; c++) {
                float p = __expf(s[i][c] - mnew);
                s[i][c] = p;
                sum += p;
            }
            sum += __shfl_xor_sync(0xffffffffu, sum, 1);
            sum += __shfl_xor_sync(0xffffffffu, sum, 2);
            sum += __shfl_xor_sync(0xffffffffu, sum, 4);
            l[i] = l[i] * alpha + sum;
            m[i] = mnew;
            al[i] = alpha;
        }

#pragma unroll
        for (int i = 0; i < 4; i++) {
            float* pr = &Ps[(r0 + i * 4) * LDP];
            *(float4*)(pr + cb0) = make_float4(s[i][0], s[i][1], s[i][2], s[i][3]);
            *(float4*)(pr + cb1) = make_float4(s[i][4], s[i][5], s[i][6], s[i][7]);
        }
        __syncwarp();

#pragma unroll
        for (int i = 0; i < 4; i++) {
            ull a2 = pack2(al[i], al[i]);
#pragma unroll
            for (int j = 0; j < 4; j++) o2[i][j] = mul2(o2[i][j], a2);
        }
        for (int k0 = 0; k0 < 64; k0 += 4) {
            float4 p4[4];
#pragma unroll
            for (int i = 0; i < 4; i++)
                p4[i] = *(const float4*)&Ps[(r0 + i * 4) * LDP + k0];
#pragma unroll
            for (int kk = 0; kk < 4; kk++) {
                const float* vr = &Vs[(k0 + kk) * LDV];
                ulonglong2 vA = *(const ulonglong2*)(vr + cb0);
                ulonglong2 vB = *(const ulonglong2*)(vr + cb1);
#pragma unroll
                for (int i = 0; i < 4; i++) {
                    float pv = (kk == 0) ? p4[i].x : (kk == 1) ? p4[i].y
                             : (kk == 2) ? p4[i].z : p4[i].w;
                    ull pa = pack2(pv, pv);
                    o2[i][0] = ffma2(pa, vA.x, o2[i][0]);
                    o2[i][1] = ffma2(pa, vA.y, o2[i][1]);
                    o2[i][2] = ffma2(pa, vB.x, o2[i][2]);
                    o2[i][3] = ffma2(pa, vB.y, o2[i][3]);
                }
            }
        }
    }

#pragma unroll
    for (int i = 0; i < 4; i++) {
        float inv = 1.0f / l[i];
        size_t row = (size_t)(b * SEQ + mt * QR + r0 + i * 4);
        float* op = O + row * DMODEL + h * HD;
        float x0, y0, x1, y1;
        unpack2(o2[i][0], x0, y0); unpack2(o2[i][1], x1, y1);
        *(float4*)&op[cb0] = make_float4(x0 * inv, y0 * inv, x1 * inv, y1 * inv);
        unpack2(o2[i][2], x0, y0); unpack2(o2[i][3], x1, y1);
        *(float4*)&op[cb1] = make_float4(x0 * inv, y0 * inv, x1 * inv, y1 * inv);
    }
}

// ---------------- launch ----------------
extern "C" void kernel_launch(void* const* d_in, const int* in_sizes, int n_in,
                              void* d_out, int out_size)
{
    const float* x    = (const float*)d_in[0];
    const float* cosT = (const float*)d_in[1];
    const float* sinT = (const float*)d_in[2];
    // d_in[3] = mask (causal, reproduced analytically)
    const float* wq   = (const float*)d_in[4];
    const float* wk   = (const float*)d_in[5];
    const float* wv   = (const float*)d_in[6];
    const float* wo   = (const float*)d_in[7];

    float* out  = (float*)d_out;
    float* knew = out + (size_t)ROWS * DMODEL;
    float* vnew = knew + (size_t)ROWS * NKV * HD;

    float *Qbuf = nullptr, *AObuf = nullptr, *KTbuf = nullptr;
    cudaGetSymbolAddress((void**)&Qbuf, g_Q);
    cudaGetSymbolAddress((void**)&AObuf, g_AO);
    cudaGetSymbolAddress((void**)&KTbuf, g_KT);
    cudaFuncSetAttribute(flash_kernel, cudaFuncAttributeMaxDynamicSharedMemorySize, FLASH_SMEM);

    // fused QKV projections (TF32 tensor cores)
    qkv_kernel<<<dim3(12, ROWS / 128), 256>>>(x, wq, wk, wv, Qbuf, knew, vnew);

    // RoPE K (in place) + K^T scratch; RoPE Q fused into flash
    rope_k_kernel<<<(ROWS * NKV * 32) / 256, 256>>>(knew, KTbuf, cosT, sinT);

    // attention (fp32)
    flash_kernel<<<dim3(SEQ / QR, BATCH * NH), 128, FLASH_SMEM>>>(
        Qbuf, KTbuf, vnew, cosT, sinT, AObuf);

    // output projection (TF32 tensor cores)
    wo_kernel<<<dim3(DMODEL / 128, ROWS / 128), 256>>>(AObuf, wo, out);
}

// round 7
// speedup vs baseline: 3.7302x; 1.7744x over previous
#include <cuda_runtime.h>
#include <cuda_bf16.h>
#include <cstddef>
#include <cstdint>

using ull = unsigned long long;

// ---------------- tf32 / mma helpers ----------------
__device__ __forceinline__ uint32_t tf32_of(float f) {
    uint32_t u; asm("cvt.rna.tf32.f32 %0, %1;" : "=r"(u) : "f"(f)); return u;
}
__device__ __forceinline__ void mma_tf32(float c[4],
    uint32_t a0, uint32_t a1, uint32_t a2, uint32_t a3,
    uint32_t b0, uint32_t b1)
{
    asm volatile("mma.sync.aligned.m16n8k8.row.col.f32.tf32.tf32.f32 "
        "{%0,%1,%2,%3}, {%4,%5,%6,%7}, {%8,%9}, {%0,%1,%2,%3};"
        : "+f"(c[0]), "+f"(c[1]), "+f"(c[2]), "+f"(c[3])
        : "r"(a0), "r"(a1), "r"(a2), "r"(a3), "r"(b0), "r"(b1));
}
__device__ __forceinline__ float ex2f(float x) {
    float r; asm("ex2.approx.f32 %0, %1;" : "=f"(r) : "f"(x)); return r;
}

// ---------------- problem constants ----------------
#define BATCH 2
#define SEQ   2048
#define DMODEL 1024
#define NH    16
#define NKV   4
#define HD    64
#define ROWS  (BATCH*SEQ)     // 4096

__device__ float g_Q[ROWS * DMODEL];   // Q after projection (rope fused into flash)
__device__ float g_AO[ROWS * DMODEL];  // attention output before Wo

// ---------------- TF32 GEMM (unchanged from R6) ----------------
#define BKT   16
#define LDAT  20
#define LDBT  136
#define AS_SZ (128 * LDAT)
#define BS_SZ (BKT * LDBT)

__device__ __forceinline__ void gemm_body_tf32(
    const float* __restrict__ A, const float* __restrict__ B, float* __restrict__ C,
    int N, int K, int brow, int bcol, uint32_t* As, uint32_t* Bs)
{
    const int tid  = threadIdx.x;
    const int w    = tid >> 5;
    const int lane = tid & 31;
    const int wm   = (w >> 2) * 64;
    const int wn   = (w & 3) * 32;
    const int qr   = lane >> 2;
    const int qc   = lane & 3;

    const int ar = tid >> 1;
    const int ak = (tid & 1) * 8;
    const int bk = tid >> 4;
    const int bc = (tid & 15) * 8;

    const float* Ap = A + (size_t)(brow + ar) * K + ak;
    const float* Bp = B + (size_t)bk * N + bcol + bc;

    float acc[4][4][4];
#pragma unroll
    for (int mt = 0; mt < 4; mt++)
#pragma unroll
        for (int nt = 0; nt < 4; nt++)
#pragma unroll
            for (int i = 0; i < 4; i++) acc[mt][nt][i] = 0.f;

    float4 ra0, ra1, rb0, rb1;
    ra0 = *(const float4*)(Ap);
    ra1 = *(const float4*)(Ap + 4);
    rb0 = *(const float4*)(Bp);
    rb1 = *(const float4*)(Bp + 4);
    {
        uint32_t* Asr = As + ar * LDAT + ak;
        uint4 av0 = make_uint4(tf32_of(ra0.x), tf32_of(ra0.y), tf32_of(ra0.z), tf32_of(ra0.w));
        uint4 av1 = make_uint4(tf32_of(ra1.x), tf32_of(ra1.y), tf32_of(ra1.z), tf32_of(ra1.w));
        *(uint4*)Asr = av0; *(uint4*)(Asr + 4) = av1;
        uint32_t* Bsr = Bs + bk * LDBT + bc;
        uint4 bv0 = make_uint4(tf32_of(rb0.x), tf32_of(rb0.y), tf32_of(rb0.z), tf32_of(rb0.w));
        uint4 bv1 = make_uint4(tf32_of(rb1.x), tf32_of(rb1.y), tf32_of(rb1.z), tf32_of(rb1.w));
        *(uint4*)Bsr = bv0; *(uint4*)(Bsr + 4) = bv1;
    }
    __syncthreads();

    int buf = 0;
    for (int k0 = 0; k0 < K; k0 += BKT) {
        const bool has_next = (k0 + BKT < K);
        if (has_next) {
            ra0 = *(const float4*)(Ap + k0 + BKT);
            ra1 = *(const float4*)(Ap + k0 + BKT + 4);
            rb0 = *(const float4*)(Bp + (size_t)(k0 + BKT) * N);
            rb1 = *(const float4*)(Bp + (size_t)(k0 + BKT) * N + 4);
        }
        const uint32_t* Asb = As + buf * AS_SZ;
        const uint32_t* Bsb = Bs + buf * BS_SZ;

#pragma unroll
        for (int kk = 0; kk < BKT; kk += 8) {
            uint32_t af[4][4];
#pragma unroll
            for (int mt = 0; mt < 4; mt++) {
                const uint32_t* ap = Asb + (wm + mt * 16 + qr) * LDAT + kk + qc;
                af[mt][0] = ap[0];
                af[mt][1] = ap[8 * LDAT];
                af[mt][2] = ap[4];
                af[mt][3] = ap[8 * LDAT + 4];
            }
            uint32_t bf[4][2];
#pragma unroll
            for (int nt = 0; nt < 4; nt++) {
                const uint32_t* bp = Bsb + (kk + qc) * LDBT + wn + nt * 8 + qr;
                bf[nt][0] = bp[0];
                bf[nt][1] = bp[4 * LDBT];
            }
#pragma unroll
            for (int mt = 0; mt < 4; mt++)
#pragma unroll
                for (int nt = 0; nt < 4; nt++)
                    mma_tf32(acc[mt][nt], af[mt][0], af[mt][1], af[mt][2], af[mt][3],
                             bf[nt][0], bf[nt][1]);
        }

        if (has_next) {
            uint32_t* Asr = As + (buf ^ 1) * AS_SZ + ar * LDAT + ak;
            uint4 av0 = make_uint4(tf32_of(ra0.x), tf32_of(ra0.y), tf32_of(ra0.z), tf32_of(ra0.w));
            uint4 av1 = make_uint4(tf32_of(ra1.x), tf32_of(ra1.y), tf32_of(ra1.z), tf32_of(ra1.w));
            *(uint4*)Asr = av0; *(uint4*)(Asr + 4) = av1;
            uint32_t* Bsr = Bs + (buf ^ 1) * BS_SZ + bk * LDBT + bc;
            uint4 bv0 = make_uint4(tf32_of(rb0.x), tf32_of(rb0.y), tf32_of(rb0.z), tf32_of(rb0.w));
            uint4 bv1 = make_uint4(tf32_of(rb1.x), tf32_of(rb1.y), tf32_of(rb1.z), tf32_of(rb1.w));
            *(uint4*)Bsr = bv0; *(uint4*)(Bsr + 4) = bv1;
        }
        __syncthreads();
        buf ^= 1;
    }

#pragma unroll
    for (int mt = 0; mt < 4; mt++) {
#pragma unroll
        for (int nt = 0; nt < 4; nt++) {
            float* crow = C + (size_t)(brow + wm + mt * 16 + qr) * N + bcol + wn + nt * 8 + 2 * qc;
            *(float2*)crow = make_float2(acc[mt][nt][0], acc[mt][nt][1]);
            *(float2*)(crow + (size_t)8 * N) = make_float2(acc[mt][nt][2], acc[mt][nt][3]);
        }
    }
}

__global__ __launch_bounds__(256) void qkv_kernel(
    const float* __restrict__ x,
    const float* __restrict__ wq, const float* __restrict__ wk, const float* __restrict__ wv,
    float* __restrict__ Qb, float* __restrict__ Kb, float* __restrict__ Vb)
{
    __shared__ uint32_t As[2 * AS_SZ];
    __shared__ uint32_t Bs[2 * BS_SZ];
    const int bx = blockIdx.x;
    const int brow = blockIdx.y * 128;
    if (bx < 8) {
        gemm_body_tf32(x, wq, Qb, DMODEL, DMODEL, brow, bx * 128, As, Bs);
    } else if (bx < 10) {
        gemm_body_tf32(x, wk, Kb, NKV * HD, DMODEL, brow, (bx - 8) * 128, As, Bs);
    } else {
        gemm_body_tf32(x, wv, Vb, NKV * HD, DMODEL, brow, (bx - 10) * 128, As, Bs);
    }
}

__global__ __launch_bounds__(256) void wo_kernel(
    const float* __restrict__ A, const float* __restrict__ B, float* __restrict__ C)
{
    __shared__ uint32_t As[2 * AS_SZ];
    __shared__ uint32_t Bs[2 * BS_SZ];
    gemm_body_tf32(A, B, C, DMODEL, DMODEL, blockIdx.y * 128, blockIdx.x * 128, As, Bs);
}

// ---------------- RoPE K (in place only; flash reads K row-major now) ----------------
__global__ void rope_k_kernel(float* __restrict__ X,
                              const float* __restrict__ cosT,
                              const float* __restrict__ sinT)
{
    int idx = blockIdx.x * blockDim.x + threadIdx.x;
    int d    = idx & 31;
    int rest = idx >> 5;
    int head = rest & (NKV - 1);
    int row  = rest >> 2;
    int s    = row & (SEQ - 1);
    float c  = cosT[s * 32 + d];
    float sn = sinT[s * 32 + d];
    float* p = X + (size_t)row * NKV * HD + head * HD + d;
    float a = p[0], bb = p[32];
    p[0]  = a * c - bb * sn;
    p[32] = bb * c + a * sn;
}

// ---------------- Flash attention v7: tf32 tensor cores ----------------
// 64q x 64k tiles, 128 threads = 4 warps, 3 CTAs/SM.
// Warp w: rows w*16..w*16+15. qr=lane>>2, qc=lane&3. R0=w*16+qr, R1=R0+8.
// Q fragments live in registers across all kt. Ps overlays Qs.
#define LDK 68
#define LDV 72
#define LDQ 68
#define LDP 68
#define QR  64
#define FLASH_SMEM ((64*LDK + 64*LDV + 64*LDQ) * 4)

__global__ __launch_bounds__(128, 3) void flash_kernel(
    const float* __restrict__ Q,    // [4096,1024] (no rope yet)
    const float* __restrict__ Kn,   // [4096,256] rope'd K (== new_k)
    const float* __restrict__ V,    // [4096,256]
    const float* __restrict__ cosT,
    const float* __restrict__ sinT,
    float* __restrict__ O)
{
    extern __shared__ uint32_t smu[];
    uint32_t* Ks = smu;                          // [key][d] tf32
    uint32_t* Vs = Ks + 64 * LDK;                // [key][d] tf32
    float*    Qs = (float*)(Vs + 64 * LDV);      // [r][d] fp32 (prologue only)
    uint32_t* Ps = (uint32_t*)Qs;                // [r][key] tf32 (overlay)

    const int tid  = threadIdx.x;
    const int w    = tid >> 5;
    const int lane = tid & 31;
    const int qr   = lane >> 2;
    const int qc   = lane & 3;
    const int R0   = w * 16 + qr;

    const int mt = gridDim.x - 1 - blockIdx.x;   // heavy blocks first
    const int bh = blockIdx.y;
    const int b  = bh >> 4;
    const int h  = bh & 15;
    const int kv = h >> 2;

    const float* Qg = Q  + (size_t)(b * SEQ + mt * QR) * DMODEL + h * HD;
    const float* Kg = Kn + (size_t)(b * SEQ) * (NKV * HD) + kv * HD;
    const float* Vg = V  + (size_t)(b * SEQ) * (NKV * HD) + kv * HD;

    // ---- Q tile: rope + scale into Qs ----
#pragma unroll
    for (int i = 0; i < 4; i++) {
        int idx = tid + i * 128;
        int r = idx >> 3;
        int d = (idx & 7) * 4;
        int s = mt * QR + r;
        float4 qa = *(const float4*)(Qg + (size_t)r * DMODEL + d);
        float4 qb = *(const float4*)(Qg + (size_t)r * DMODEL + d + 32);
        float4 c  = *(const float4*)(cosT + s * 32 + d);
        float4 sn = *(const float4*)(sinT + s * 32 + d);
        float4 lo, hi;
        lo.x = (qa.x * c.x - qb.x * sn.x) * 0.125f;
        lo.y = (qa.y * c.y - qb.y * sn.y) * 0.125f;
        lo.z = (qa.z * c.z - qb.z * sn.z) * 0.125f;
        lo.w = (qa.w * c.w - qb.w * sn.w) * 0.125f;
        hi.x = (qb.x * c.x + qa.x * sn.x) * 0.125f;
        hi.y = (qb.y * c.y + qa.y * sn.y) * 0.125f;
        hi.z = (qb.z * c.z + qa.z * sn.z) * 0.125f;
        hi.w = (qb.w * c.w + qa.w * sn.w) * 0.125f;
        *(float4*)&Qs[r * LDQ + d]      = lo;
        *(float4*)&Qs[r * LDQ + d + 32] = hi;
    }
    __syncthreads();

    // ---- Q fragments to registers (tf32) ----
    uint32_t qf[8][4];
#pragma unroll
    for (int kb = 0; kb < 8; kb++) {
        qf[kb][0] = tf32_of(Qs[R0 * LDQ + kb * 8 + qc]);
        qf[kb][1] = tf32_of(Qs[(R0 + 8) * LDQ + kb * 8 + qc]);
        qf[kb][2] = tf32_of(Qs[R0 * LDQ + kb * 8 + qc + 4]);
        qf[kb][3] = tf32_of(Qs[(R0 + 8) * LDQ + kb * 8 + qc + 4]);
    }
    __syncthreads();   // Qs dead; Ps overlay now safe

    float oacc[8][4];
#pragma unroll
    for (int nt = 0; nt < 8; nt++)
#pragma unroll
        for (int i = 0; i < 4; i++) oacc[nt][i] = 0.f;
    float m0 = -1e30f, m1 = -1e30f, l0 = 0.f, l1 = 0.f;
    const float L2E = 1.4426950408889634f;

    for (int kt = 0; kt <= mt; kt++) {
        __syncthreads();   // prior iter's Ks/Vs/Ps reads complete
        // ---- load K,V tiles (tf32 convert at store) ----
#pragma unroll
        for (int i = 0; i < 8; i++) {
            int idx = tid + i * 128;
            int r  = idx >> 4;
            int c4 = (idx & 15) * 4;
            size_t grow = (size_t)(kt * 64 + r) * (NKV * HD);
            float4 kk4 = *(const float4*)(Kg + grow + c4);
            Ks[r * LDK + c4 + 0] = tf32_of(kk4.x);
            Ks[r * LDK + c4 + 1] = tf32_of(kk4.y);
            Ks[r * LDK + c4 + 2] = tf32_of(kk4.z);
            Ks[r * LDK + c4 + 3] = tf32_of(kk4.w);
            float4 vv4 = *(const float4*)(Vg + grow + c4);
            Vs[r * LDV + c4 + 0] = tf32_of(vv4.x);
            Vs[r * LDV + c4 + 1] = tf32_of(vv4.y);
            Vs[r * LDV + c4 + 2] = tf32_of(vv4.z);
            Vs[r * LDV + c4 + 3] = tf32_of(vv4.w);
        }
        __syncthreads();

        // ---- S = Q @ K^T (tensor) ----
        float sacc[8][4];
#pragma unroll
        for (int nt = 0; nt < 8; nt++)
#pragma unroll
            for (int i = 0; i < 4; i++) sacc[nt][i] = 0.f;

#pragma unroll
        for (int kb = 0; kb < 8; kb++) {
#pragma unroll
            for (int nt = 0; nt < 8; nt++) {
                uint32_t b0 = Ks[(nt * 8 + qr) * LDK + kb * 8 + qc];
                uint32_t b1 = Ks[(nt * 8 + qr) * LDK + kb * 8 + qc + 4];
                mma_tf32(sacc[nt], qf[kb][0], qf[kb][1], qf[kb][2], qf[kb][3], b0, b1);
            }
        }

        // ---- causal mask (diag tile) ----
        if (kt == mt) {
#pragma unroll
            for (int nt = 0; nt < 8; nt++) {
                int c0 = nt * 8 + 2 * qc, c1 = c0 + 1;
                if (c0 > R0)     sacc[nt][0] = -60.f;
                if (c1 > R0)     sacc[nt][1] = -60.f;
                if (c0 > R0 + 8) sacc[nt][2] = -60.f;
                if (c1 > R0 + 8) sacc[nt][3] = -60.f;
            }
        }

        // ---- online softmax (rows R0, R1; reduce over 4 qc lanes) ----
        float mx0 = -1e30f, mx1 = -1e30f;
#pragma unroll
        for (int nt = 0; nt < 8; nt++) {
            mx0 = fmaxf(mx0, fmaxf(sacc[nt][0], sacc[nt][1]));
            mx1 = fmaxf(mx1, fmaxf(sacc[nt][2], sacc[nt][3]));
        }
        mx0 = fmaxf(mx0, __shfl_xor_sync(0xffffffffu, mx0, 1));
        mx0 = fmaxf(mx0, __shfl_xor_sync(0xffffffffu, mx0, 2));
        mx1 = fmaxf(mx1, __shfl_xor_sync(0xffffffffu, mx1, 1));
        mx1 = fmaxf(mx1, __shfl_xor_sync(0xffffffffu, mx1, 2));
        float nm0 = fmaxf(m0, mx0), nm1 = fmaxf(m1, mx1);
        float al0 = ex2f((m0 - nm0) * L2E);
        float al1 = ex2f((m1 - nm1) * L2E);
        float mo0 = -nm0 * L2E, mo1 = -nm1 * L2E;

        float sum0 = 0.f, sum1 = 0.f;
#pragma unroll
        for (int nt = 0; nt < 8; nt++) {
            float e00 = ex2f(fmaf(sacc[nt][0], L2E, mo0));
            float e01 = ex2f(fmaf(sacc[nt][1], L2E, mo0));
            float e10 = ex2f(fmaf(sacc[nt][2], L2E, mo1));
            float e11 = ex2f(fmaf(sacc[nt][3], L2E, mo1));
            sum0 += e00 + e01;
            sum1 += e10 + e11;
            ull pr0 = ((ull)tf32_of(e01) << 32) | tf32_of(e00);
            ull pr1 = ((ull)tf32_of(e11) << 32) | tf32_of(e10);
            *(ull*)&Ps[R0 * LDP + nt * 8 + 2 * qc]       = pr0;
            *(ull*)&Ps[(R0 + 8) * LDP + nt * 8 + 2 * qc] = pr1;
        }
        sum0 += __shfl_xor_sync(0xffffffffu, sum0, 1);
        sum0 += __shfl_xor_sync(0xffffffffu, sum0, 2);
        sum1 += __shfl_xor_sync(0xffffffffu, sum1, 1);
        sum1 += __shfl_xor_sync(0xffffffffu, sum1, 2);
        l0 = l0 * al0 + sum0;  m0 = nm0;
        l1 = l1 * al1 + sum1;  m1 = nm1;
        __syncwarp();   // P rows warp-local: make stores visible to warp

        // ---- rescale O, then O += P @ V (tensor) ----
#pragma unroll
        for (int nt = 0; nt < 8; nt++) {
            oacc[nt][0] *= al0; oacc[nt][1] *= al0;
            oacc[nt][2] *= al1; oacc[nt][3] *= al1;
        }
#pragma unroll
        for (int kb = 0; kb < 8; kb++) {
            uint32_t a0 = Ps[R0 * LDP + kb * 8 + qc];
            uint32_t a1 = Ps[(R0 + 8) * LDP + kb * 8 + qc];
            uint32_t a2 = Ps[R0 * LDP + kb * 8 + qc + 4];
            uint32_t a3 = Ps[(R0 + 8) * LDP + kb * 8 + qc + 4];
#pragma unroll
            for (int nt = 0; nt < 8; nt++) {
                uint32_t b0 = Vs[(kb * 8 + qc) * LDV + nt * 8 + qr];
                uint32_t b1 = Vs[(kb * 8 + qc + 4) * LDV + nt * 8 + qr];
                mma_tf32(oacc[nt], a0, a1, a2, a3, b0, b1);
            }
        }
    }

    // ---- epilogue: O /= l ----
    float inv0 = 1.0f / l0, inv1 = 1.0f / l1;
    size_t row0 = (size_t)(b * SEQ + mt * QR + R0);
#pragma unroll
    for (int nt = 0; nt < 8; nt++) {
        float* op0 = O + row0 * DMODEL + h * HD + nt * 8 + 2 * qc;
        float* op1 = op0 + (size_t)8 * DMODEL;
        *(float2*)op0 = make_float2(oacc[nt][0] * inv0, oacc[nt][1] * inv0);
        *(float2*)op1 = make_float2(oacc[nt][2] * inv1, oacc[nt][3] * inv1);
    }
}

// ---------------- launch ----------------
extern "C" void kernel_launch(void* const* d_in, const int* in_sizes, int n_in,
                              void* d_out, int out_size)
{
    const float* x    = (const float*)d_in[0];
    const float* cosT = (const float*)d_in[1];
    const float* sinT = (const float*)d_in[2];
    // d_in[3] = mask (causal, reproduced analytically)
    const float* wq   = (const float*)d_in[4];
    const float* wk   = (const float*)d_in[5];
    const float* wv   = (const float*)d_in[6];
    const float* wo   = (const float*)d_in[7];

    float* out  = (float*)d_out;
    float* knew = out + (size_t)ROWS * DMODEL;
    float* vnew = knew + (size_t)ROWS * NKV * HD;

    float *Qbuf = nullptr, *AObuf = nullptr;
    cudaGetSymbolAddress((void**)&Qbuf, g_Q);
    cudaGetSymbolAddress((void**)&AObuf, g_AO);
    cudaFuncSetAttribute(flash_kernel, cudaFuncAttributeMaxDynamicSharedMemorySize, FLASH_SMEM);

    // fused QKV projections (TF32 tensor cores)
    qkv_kernel<<<dim3(12, ROWS / 128), 256>>>(x, wq, wk, wv, Qbuf, knew, vnew);

    // RoPE K in place (flash reads new_k row-major directly)
    rope_k_kernel<<<(ROWS * NKV * 32) / 256, 256>>>(knew, cosT, sinT);

    // attention (TF32 tensor cores, fp32 softmax)
    flash_kernel<<<dim3(SEQ / QR, BATCH * NH), 128, FLASH_SMEM>>>(
        Qbuf, knew, vnew, cosT, sinT, AObuf);

    // output projection (TF32 tensor cores)
    wo_kernel<<<dim3(DMODEL / 128, ROWS / 128), 256>>>(AObuf, wo, out);
}